// round 7
// baseline (speedup 1.0000x reference)
#include <cuda_runtime.h>
#include <cuda_bf16.h>
#include <cuda_fp16.h>
#include <cstdint>

#define NUM_NODES 100000
#define HIDDEN    128
#define OFFS      2
#define MAX_E     1700000
#define MAX_SEQ   32768

// ---------------- device scratch ----------------
__device__ int   g_deg[NUM_NODES];
__device__ int   g_fill[NUM_NODES];
__device__ int   g_rowptr[NUM_NODES + 1];
__device__ int   g_blksum[2048];
__device__ int   g_colidx[MAX_E];
__device__ float g_dinv[NUM_NODES];
__device__ int   g_need[NUM_NODES];
__device__ int   g_slot[NUM_NODES];
__device__ int   g_list[MAX_SEQ];
__device__ int   g_cnt;
__device__ unsigned g_bar;   // zero-init; self-restoring
__device__ unsigned g_gen;   // monotonic
__device__ __half g_emb16[(size_t)NUM_NODES * HIDDEN];
__device__ __half g_h16[(size_t)NUM_NODES * HIDDEN];
__device__ float  g_z[(size_t)MAX_SEQ * HIDDEN];
__device__ __nv_bfloat16 g_w0h[HIDDEN * HIDDEN];  // W^T [n][k]
__device__ __nv_bfloat16 g_w0l[HIDDEN * HIDDEN];
__device__ __nv_bfloat16 g_w1h[HIDDEN * HIDDEN];
__device__ __nv_bfloat16 g_w1l[HIDDEN * HIDDEN];

// ---------------- helpers ----------------
__device__ __forceinline__ uint32_t smem_u32(const void* p) {
    uint32_t a;
    asm("{ .reg .u64 t; cvta.to.shared.u64 t, %1; cvt.u32.u64 %0, t; }" : "=r"(a) : "l"(p));
    return a;
}
__device__ __forceinline__ void ldsm_x4(uint32_t addr, uint32_t& r0, uint32_t& r1,
                                        uint32_t& r2, uint32_t& r3) {
    asm volatile("ldmatrix.sync.aligned.m8n8.x4.shared.b16 {%0,%1,%2,%3}, [%4];"
                 : "=r"(r0), "=r"(r1), "=r"(r2), "=r"(r3) : "r"(addr));
}
__device__ __forceinline__ void mma_bf16(float* c, const uint32_t* a, uint32_t b0, uint32_t b1) {
    asm volatile(
        "mma.sync.aligned.m16n8k16.row.col.f32.bf16.bf16.f32 "
        "{%0,%1,%2,%3}, {%4,%5,%6,%7}, {%8,%9}, {%0,%1,%2,%3};"
        : "+f"(c[0]), "+f"(c[1]), "+f"(c[2]), "+f"(c[3])
        : "r"(a[0]), "r"(a[1]), "r"(a[2]), "r"(a[3]), "r"(b0), "r"(b1));
}
__device__ __forceinline__ float4 ld_h4(const __half* __restrict__ x, size_t idx4) {
    uint2 u = reinterpret_cast<const uint2*>(x)[idx4];
    __half2 a = *reinterpret_cast<__half2*>(&u.x);
    __half2 b = *reinterpret_cast<__half2*>(&u.y);
    float2 fa = __half22float2(a), fb = __half22float2(b);
    return make_float4(fa.x, fa.y, fb.x, fb.y);
}

// software grid barrier (all blocks co-resident by construction)
__device__ __forceinline__ void grid_barrier(int nblk) {
    __syncthreads();
    if (threadIdx.x == 0) {
        __threadfence();
        unsigned gen = *(volatile unsigned*)&g_gen;   // read BEFORE arriving
        if (atomicAdd(&g_bar, 1u) == (unsigned)nblk - 1u) {
            atomicExch(&g_bar, 0u);
            __threadfence();
            atomicAdd(&g_gen, 1u);
        } else {
            while (*(volatile unsigned*)&g_gen == gen) { __nanosleep(64); }
            __threadfence();
        }
    }
    __syncthreads();
}

// ---------------- persistent prep: all CSR/prep phases in ONE kernel ----------------
__global__ __launch_bounds__(256, 4)
void k_prep(const float* __restrict__ emb, const float* __restrict__ W0,
            const float* __restrict__ W1, const int* __restrict__ src,
            const int* __restrict__ dst, const int* __restrict__ seq,
            int E, int S, int nblk, int chunk) {
    const int tid = threadIdx.x, bid = blockIdx.x;
    const int gtid = bid * 256 + tid;
    const int gstride = nblk * 256;
    __shared__ int sbuf[256];

    // ---- P0: zero counters, split weights, convert emb to fp16 ----
    for (int i = gtid; i < NUM_NODES; i += gstride) {
        g_deg[i] = 0; g_fill[i] = 0; g_need[i] = 0;
    }
    if (gtid == 0) g_cnt = 0;
    for (int i = gtid; i < 2 * HIDDEN * HIDDEN; i += gstride) {
        int which = i >> 14, idx = i & 16383;     // idx = k*128+n
        float w = (which ? W1 : W0)[idx];
        int k = idx >> 7, n = idx & 127;
        __nv_bfloat16 h = __float2bfloat16(w);
        (which ? g_w1h : g_w0h)[n * 128 + k] = h;
        (which ? g_w1l : g_w0l)[n * 128 + k] = __float2bfloat16(w - __bfloat162float(h));
    }
    for (int i = gtid; i < NUM_NODES * 32; i += gstride) {
        float4 v = reinterpret_cast<const float4*>(emb)[i];
        __half2 h0 = __floats2half2_rn(v.x, v.y);
        __half2 h1 = __floats2half2_rn(v.z, v.w);
        uint2 u;
        u.x = *reinterpret_cast<uint32_t*>(&h0);
        u.y = *reinterpret_cast<uint32_t*>(&h1);
        reinterpret_cast<uint2*>(g_emb16)[i] = u;
    }
    grid_barrier(nblk);

    // ---- P1: degree count + mark needed ----
    for (int e = gtid; e < E; e += gstride) atomicAdd(&g_deg[dst[e]], 1);
    for (int p = gtid; p < S; p += gstride) {
        int v = seq[p];
        if (v >= 0) g_need[v] = 1;
    }
    grid_barrier(nblk);

    // ---- P2: per-block chunk sums ----
    {
        int start = bid * chunk;
        int len = NUM_NODES - start;
        if (len > chunk) len = chunk;
        int acc = 0;
        for (int i = tid; i < len; i += 256) acc += g_deg[start + i];
        sbuf[tid] = acc;
        __syncthreads();
        #pragma unroll
        for (int off = 128; off > 0; off >>= 1) {
            if (tid < off) sbuf[tid] += sbuf[tid + off];
            __syncthreads();
        }
        if (tid == 0) g_blksum[bid] = sbuf[0];
    }
    grid_barrier(nblk);

    // ---- P3: block 0 exclusive-scans the nblk chunk sums ----
    if (bid == 0) {
        int ele = (nblk + 255) >> 8;              // elements per thread (<=8)
        int base_i = tid * ele;
        int vals[8];
        int tsum = 0;
        for (int q = 0; q < ele && q < 8; q++) {
            int ii = base_i + q;
            vals[q] = (ii < nblk) ? g_blksum[ii] : 0;
            tsum += vals[q];
        }
        sbuf[tid] = tsum;
        __syncthreads();
        #pragma unroll
        for (int off = 1; off < 256; off <<= 1) {
            int t = (tid >= off) ? sbuf[tid - off] : 0;
            __syncthreads();
            sbuf[tid] += t;
            __syncthreads();
        }
        int run = sbuf[tid] - tsum;               // exclusive prefix
        for (int q = 0; q < ele && q < 8; q++) {
            int ii = base_i + q;
            if (ii < nblk) g_blksum[ii] = run;
            run += vals[q];
        }
    }
    grid_barrier(nblk);

    // ---- P4: per-block chunk exclusive scan -> rowptr, dinv, compact list ----
    {
        int start = bid * chunk;
        int len = NUM_NODES - start;
        if (len > chunk) len = chunk;
        if (len < 0) len = 0;
        int run = (start < NUM_NODES) ? g_blksum[bid] : 0;
        for (int base = 0; base < chunk; base += 256) {
            int li  = base + tid;
            int idx = start + li;
            int val = (li < len) ? g_deg[idx] : 0;
            sbuf[tid] = val;
            __syncthreads();
            #pragma unroll
            for (int off = 1; off < 256; off <<= 1) {
                int t = (tid >= off) ? sbuf[tid - off] : 0;
                __syncthreads();
                sbuf[tid] += t;
                __syncthreads();
            }
            int excl = sbuf[tid] - val;
            if (li < len) {
                g_rowptr[idx] = run + excl;
                g_dinv[idx] = rsqrtf((float)(val + 1));  // +1 self loop
                if (g_need[idx]) {
                    int s = atomicAdd(&g_cnt, 1);
                    g_slot[idx] = s;
                    g_list[s] = idx;
                }
            }
            int tot = sbuf[255];
            __syncthreads();
            run += tot;
        }
        if (gtid == 0) g_rowptr[NUM_NODES] = E;
    }
    grid_barrier(nblk);

    // ---- P5: fill CSR ----
    for (int e = gtid; e < E; e += gstride) {
        int d = dst[e];
        int p = g_rowptr[d] + atomicAdd(&g_fill[d], 1);
        g_colidx[p] = src[e];
    }
}

// ---------------- fused layer: aggregate 128 rows into smem, then tensor GEMM ----------------
#define LDS_STRIDE 136
#define TILE_HALFS (128 * LDS_STRIDE)
#define LAYER_SMEM (4 * TILE_HALFS * 2)

template <bool RELU, bool COMPACT, bool HOUT>
__global__ __launch_bounds__(256)
void k_layer(const __half* __restrict__ x,
             const __nv_bfloat16* __restrict__ Bh, const __nv_bfloat16* __restrict__ Bl,
             const float* __restrict__ bias, void* __restrict__ Cv, int Mfix) {
    const int M = COMPACT ? g_cnt : Mfix;
    const int brow = blockIdx.x * 128;
    if (brow >= M) return;

    extern __shared__ __align__(16) __nv_bfloat16 sm[];
    __nv_bfloat16* sAh = sm;
    __nv_bfloat16* sAl = sm + TILE_HALFS;
    __nv_bfloat16* sBh = sm + 2 * TILE_HALFS;
    __nv_bfloat16* sBl = sm + 3 * TILE_HALFS;

    const int tid = threadIdx.x, wid = tid >> 5, lane = tid & 31;

    // weight tiles -> smem (issued first; independent of agg)
    for (int i = tid; i < 2048; i += 256) {
        int r = i >> 4, c8 = (i & 15) << 3;
        int d = r * LDS_STRIDE + c8;
        *reinterpret_cast<uint4*>(sBh + d) =
            *reinterpret_cast<const uint4*>(Bh + (size_t)r * 128 + c8);
        *reinterpret_cast<uint4*>(sBl + d) =
            *reinterpret_cast<const uint4*>(Bl + (size_t)r * 128 + c8);
    }

    // ---- aggregation: warp owns local rows [wid*16, wid*16+16), pipelined ----
    {
        const int lr0 = wid * 16;
        // next-node prefetch state
        int nB = 0, nE = 0;
        float nDv = 0.f, nW = 0.f;
        float4 nSelf = make_float4(0.f, 0.f, 0.f, 0.f);
        int nC = 0;
        bool nVal = false;

        // fetch node li's header (macro-ish lambda)
        auto fetch = [&](int li) {
            int grow = brow + lr0 + li;
            nVal = grow < M;
            int nd = 0;
            if (nVal) nd = COMPACT ? g_list[grow] : grow;
            if (nVal) {
                nDv = g_dinv[nd];
                nB = g_rowptr[nd];
                nE = g_rowptr[nd + 1];
                nSelf = ld_h4(x, (size_t)nd * 32 + lane);
                int m = min(32, nE - nB);
                nC = (lane < m) ? g_colidx[nB + lane] : 0;
                nW = (lane < m) ? g_dinv[nC] * nDv : 0.f;
            } else {
                nDv = 0.f; nB = 0; nE = 0; nC = 0; nW = 0.f;
                nSelf = make_float4(0.f, 0.f, 0.f, 0.f);
            }
        };
        fetch(0);

        for (int li = 0; li < 16; li++) {
            // consume current, prefetch next
            bool  val = nVal;
            float dv  = nDv;
            int   b = nB, e = nE;
            float4 self = nSelf;
            int   c = nC;
            float w = nW;
            if (li < 15) fetch(li + 1);

            float ws = dv * dv;
            float4 acc = make_float4(self.x * ws, self.y * ws, self.z * ws, self.w * ws);
            if (val) {
                for (int base = b; base < e; base += 32) {
                    int m = min(32, e - base);
                    if (base != b) {   // reload for extra batches (rare)
                        c = (lane < m) ? g_colidx[base + lane] : 0;
                        w = (lane < m) ? g_dinv[c] * dv : 0.f;
                    }
                    int j = 0;
                    for (; j + 4 <= m; j += 4) {
                        int   s0 = __shfl_sync(0xFFFFFFFFu, c, j);
                        int   s1 = __shfl_sync(0xFFFFFFFFu, c, j + 1);
                        int   s2 = __shfl_sync(0xFFFFFFFFu, c, j + 2);
                        int   s3 = __shfl_sync(0xFFFFFFFFu, c, j + 3);
                        float w0 = __shfl_sync(0xFFFFFFFFu, w, j);
                        float w1 = __shfl_sync(0xFFFFFFFFu, w, j + 1);
                        float w2 = __shfl_sync(0xFFFFFFFFu, w, j + 2);
                        float w3 = __shfl_sync(0xFFFFFFFFu, w, j + 3);
                        float4 v0 = ld_h4(x, (size_t)s0 * 32 + lane);
                        float4 v1 = ld_h4(x, (size_t)s1 * 32 + lane);
                        float4 v2 = ld_h4(x, (size_t)s2 * 32 + lane);
                        float4 v3 = ld_h4(x, (size_t)s3 * 32 + lane);
                        acc.x += v0.x * w0 + v1.x * w1 + v2.x * w2 + v3.x * w3;
                        acc.y += v0.y * w0 + v1.y * w1 + v2.y * w2 + v3.y * w3;
                        acc.z += v0.z * w0 + v1.z * w1 + v2.z * w2 + v3.z * w3;
                        acc.w += v0.w * w0 + v1.w * w1 + v2.w * w2 + v3.w * w3;
                    }
                    for (; j < m; j++) {
                        int   s0 = __shfl_sync(0xFFFFFFFFu, c, j);
                        float w0 = __shfl_sync(0xFFFFFFFFu, w, j);
                        float4 v0 = ld_h4(x, (size_t)s0 * 32 + lane);
                        acc.x += v0.x * w0; acc.y += v0.y * w0;
                        acc.z += v0.z * w0; acc.w += v0.w * w0;
                    }
                }
            }
            // split to bf16 hi/lo, store into smem A tiles
            float vv[4] = {acc.x, acc.y, acc.z, acc.w};
            ushort4 sh, sl;
            unsigned short* ph = &sh.x;
            unsigned short* pl = &sl.x;
            #pragma unroll
            for (int cc = 0; cc < 4; cc++) {
                __nv_bfloat16 hh = __float2bfloat16(vv[cc]);
                __nv_bfloat16 ll = __float2bfloat16(vv[cc] - __bfloat162float(hh));
                ph[cc] = __bfloat16_as_ushort(hh);
                pl[cc] = __bfloat16_as_ushort(ll);
            }
            int srow = (lr0 + li) * LDS_STRIDE + lane * 4;
            *reinterpret_cast<ushort4*>(sAh + srow) = sh;
            *reinterpret_cast<ushort4*>(sAl + srow) = sl;
        }
    }
    __syncthreads();

    // ---- GEMM: 3-pass bf16x3, warps: 4 along M x 2 along N ----
    const int mb = (wid & 3) * 32;
    const int nb = (wid >> 2) * 64;

    float acc[2][8][4];
    #pragma unroll
    for (int i = 0; i < 2; i++)
        #pragma unroll
        for (int j = 0; j < 8; j++)
            #pragma unroll
            for (int q = 0; q < 4; q++) acc[i][j][q] = 0.0f;

    const int lrow  = lane & 15;
    const int lbyte = (lane >> 4) << 4;

    #pragma unroll
    for (int pass = 0; pass < 3; pass++) {
        const __nv_bfloat16* pA = (pass == 1) ? sAl : sAh;
        const __nv_bfloat16* pB = (pass == 2) ? sBl : sBh;
        #pragma unroll
        for (int k16 = 0; k16 < 8; k16++) {
            int kb = k16 * 16;
            uint32_t a[2][4];
            #pragma unroll
            for (int i = 0; i < 2; i++) {
                uint32_t ad = smem_u32(pA + (mb + i * 16 + lrow) * LDS_STRIDE + kb) + lbyte;
                ldsm_x4(ad, a[i][0], a[i][1], a[i][2], a[i][3]);
            }
            uint32_t b[4][4];
            #pragma unroll
            for (int j = 0; j < 4; j++) {
                uint32_t ad = smem_u32(pB + (nb + j * 16 + lrow) * LDS_STRIDE + kb) + lbyte;
                ldsm_x4(ad, b[j][0], b[j][1], b[j][2], b[j][3]);
            }
            #pragma unroll
            for (int i = 0; i < 2; i++)
                #pragma unroll
                for (int j = 0; j < 4; j++) {
                    mma_bf16(acc[i][j * 2 + 0], a[i], b[j][0], b[j][2]);
                    mma_bf16(acc[i][j * 2 + 1], a[i], b[j][1], b[j][3]);
                }
        }
    }

    const int tr = lane >> 2, tc = (lane & 3) * 2;
    #pragma unroll
    for (int i = 0; i < 2; i++) {
        #pragma unroll
        for (int j = 0; j < 8; j++) {
            int col = nb + j * 8 + tc;
            float bx = bias[col], by = bias[col + 1];
            int row0 = brow + mb + i * 16 + tr;
            float2 o0, o1;
            o0.x = acc[i][j][0] + bx; o0.y = acc[i][j][1] + by;
            o1.x = acc[i][j][2] + bx; o1.y = acc[i][j][3] + by;
            if (RELU) {
                o0.x = fmaxf(o0.x, 0.f); o0.y = fmaxf(o0.y, 0.f);
                o1.x = fmaxf(o1.x, 0.f); o1.y = fmaxf(o1.y, 0.f);
            }
            if (HOUT) {
                __half* C = (__half*)Cv;
                if (row0 < M)
                    *reinterpret_cast<__half2*>(C + (size_t)row0 * 128 + col) =
                        __floats2half2_rn(o0.x, o0.y);
                if (row0 + 8 < M)
                    *reinterpret_cast<__half2*>(C + (size_t)(row0 + 8) * 128 + col) =
                        __floats2half2_rn(o1.x, o1.y);
            } else {
                float* C = (float*)Cv;
                if (row0 < M)
                    *reinterpret_cast<float2*>(C + (size_t)row0 * 128 + col) = o0;
                if (row0 + 8 < M)
                    *reinterpret_cast<float2*>(C + (size_t)(row0 + 8) * 128 + col) = o1;
            }
        }
    }
}

// ---------------- final gather ----------------
__global__ __launch_bounds__(256)
void k_gather(const float* __restrict__ z, const float* __restrict__ emb,
              const int* __restrict__ seq, float* __restrict__ out, int S) {
    int t = blockIdx.x * blockDim.x + threadIdx.x;
    int pos = t >> 5, lane = t & 31;
    if (pos >= S) return;
    int v = seq[pos];
    const float4* srcp;
    size_t row;
    if (v >= 0) { srcp = reinterpret_cast<const float4*>(z);   row = (size_t)g_slot[v]; }
    else        { srcp = reinterpret_cast<const float4*>(emb); row = (size_t)(v + OFFS + NUM_NODES); }
    reinterpret_cast<float4*>(out)[(size_t)pos * 32 + lane] = srcp[row * 32 + lane];
}

// ---------------- host launch ----------------
extern "C" void kernel_launch(void* const* d_in, const int* in_sizes, int n_in,
                              void* d_out, int out_size) {
    const float* emb = (const float*)d_in[0];
    const float* W0  = (const float*)d_in[1];
    const float* b0  = (const float*)d_in[2];
    const float* W1  = (const float*)d_in[3];
    const float* b1  = (const float*)d_in[4];
    const int*   ei  = (const int*)d_in[5];
    const int*   seq = (const int*)d_in[6];

    int E = in_sizes[5] / 2;
    int S = in_sizes[6];
    const int* src = ei;
    const int* dst = ei + E;

    float *z = nullptr;
    __half *emb16 = nullptr, *h16 = nullptr;
    __nv_bfloat16 *w0h = nullptr, *w0l = nullptr, *w1h = nullptr, *w1l = nullptr;
    cudaGetSymbolAddress((void**)&z,     g_z);
    cudaGetSymbolAddress((void**)&emb16, g_emb16);
    cudaGetSymbolAddress((void**)&h16,   g_h16);
    cudaGetSymbolAddress((void**)&w0h,   g_w0h);
    cudaGetSymbolAddress((void**)&w0l,   g_w0l);
    cudaGetSymbolAddress((void**)&w1h,   g_w1h);
    cudaGetSymbolAddress((void**)&w1l,   g_w1l);

    cudaFuncSetAttribute((const void*)k_layer<true, false, true>,
                         cudaFuncAttributeMaxDynamicSharedMemorySize, LAYER_SMEM);
    cudaFuncSetAttribute((const void*)k_layer<false, true, false>,
                         cudaFuncAttributeMaxDynamicSharedMemorySize, LAYER_SMEM);

    // persistent-prep grid: guaranteed co-resident blocks
    int dev = 0, nsm = 0, occ = 0;
    cudaGetDevice(&dev);
    cudaDeviceGetAttribute(&nsm, cudaDevAttrMultiProcessorCount, dev);
    cudaOccupancyMaxActiveBlocksPerMultiprocessor(&occ, k_prep, 256, 0);
    if (occ < 1) occ = 1;
    if (occ > 8) occ = 8;
    int nblk  = nsm * occ;
    if (nblk > 2048) nblk = 2048;
    int chunk = (NUM_NODES + nblk - 1) / nblk;

    // 1) all prep in one persistent kernel
    k_prep<<<nblk, 256>>>(emb, W0, W1, src, dst, seq, E, S, nblk, chunk);
    // 2) layer 1: agg(all nodes) + GEMM fused, h written fp16
    k_layer<true, false, true><<<(NUM_NODES + 127) / 128, 256, LAYER_SMEM>>>(
        emb16, w0h, w0l, b0, h16, NUM_NODES);
    // 3) layer 2: agg(needed nodes) + GEMM fused, compact z fp32
    k_layer<false, true, false><<<(MAX_SEQ + 127) / 128, 256, LAYER_SMEM>>>(
        h16, w1h, w1l, b1, z, 0);
    // 4) gather
    k_gather<<<(S * 32 + 255) / 256, 256>>>(z, emb, seq, (float*)d_out, S);
}

// round 9
// speedup vs baseline: 1.5856x; 1.5856x over previous
#include <cuda_runtime.h>
#include <cuda_bf16.h>
#include <cuda_fp16.h>
#include <cstdint>

#define NUM_NODES 100000
#define HIDDEN    128
#define OFFS      2
#define MAX_E     1700000
#define MAX_SEQ   32768

// ---------------- device scratch ----------------
__device__ int   g_deg[NUM_NODES];
__device__ int   g_fill[NUM_NODES];
__device__ int   g_rowptr[NUM_NODES + 1];
__device__ int   g_blksum[2048];
__device__ int   g_colidx[MAX_E];
__device__ float g_dinv[NUM_NODES];
__device__ int   g_need[NUM_NODES];
__device__ int   g_slot[NUM_NODES];
__device__ int   g_list[MAX_SEQ];
__device__ int   g_cnt;
__device__ unsigned g_bar;   // zero-init; self-restoring
__device__ unsigned g_gen;   // monotonic
__device__ __half g_y16[(size_t)NUM_NODES * HIDDEN];   // Y = X @ W (pre-agg), reused per layer
__device__ __half g_h16[(size_t)NUM_NODES * HIDDEN];   // h = relu(A·Y0 + b0)
__device__ float  g_z[(size_t)MAX_SEQ * HIDDEN];       // compact layer-2 out
__device__ __nv_bfloat16 g_w0h[HIDDEN * HIDDEN];       // W^T [n][k] hi/lo
__device__ __nv_bfloat16 g_w0l[HIDDEN * HIDDEN];
__device__ __nv_bfloat16 g_w1h[HIDDEN * HIDDEN];
__device__ __nv_bfloat16 g_w1l[HIDDEN * HIDDEN];

// ---------------- helpers ----------------
__device__ __forceinline__ uint32_t smem_u32(const void* p) {
    uint32_t a;
    asm("{ .reg .u64 t; cvta.to.shared.u64 t, %1; cvt.u32.u64 %0, t; }" : "=r"(a) : "l"(p));
    return a;
}
__device__ __forceinline__ void ldsm_x4(uint32_t addr, uint32_t& r0, uint32_t& r1,
                                        uint32_t& r2, uint32_t& r3) {
    asm volatile("ldmatrix.sync.aligned.m8n8.x4.shared.b16 {%0,%1,%2,%3}, [%4];"
                 : "=r"(r0), "=r"(r1), "=r"(r2), "=r"(r3) : "r"(addr));
}
__device__ __forceinline__ void mma_bf16(float* c, const uint32_t* a, uint32_t b0, uint32_t b1) {
    asm volatile(
        "mma.sync.aligned.m16n8k16.row.col.f32.bf16.bf16.f32 "
        "{%0,%1,%2,%3}, {%4,%5,%6,%7}, {%8,%9}, {%0,%1,%2,%3};"
        : "+f"(c[0]), "+f"(c[1]), "+f"(c[2]), "+f"(c[3])
        : "r"(a[0]), "r"(a[1]), "r"(a[2]), "r"(a[3]), "r"(b0), "r"(b1));
}
__device__ __forceinline__ float4 ld_h4(const __half* __restrict__ x, size_t idx4) {
    uint2 u = reinterpret_cast<const uint2*>(x)[idx4];
    __half2 a = *reinterpret_cast<__half2*>(&u.x);
    __half2 b = *reinterpret_cast<__half2*>(&u.y);
    float2 fa = __half22float2(a), fb = __half22float2(b);
    return make_float4(fa.x, fa.y, fb.x, fb.y);
}
__device__ __forceinline__ void grid_barrier(int nblk) {
    __syncthreads();
    if (threadIdx.x == 0) {
        __threadfence();
        unsigned gen = *(volatile unsigned*)&g_gen;
        if (atomicAdd(&g_bar, 1u) == (unsigned)nblk - 1u) {
            atomicExch(&g_bar, 0u);
            __threadfence();
            atomicAdd(&g_gen, 1u);
        } else {
            while (*(volatile unsigned*)&g_gen == gen) { __nanosleep(64); }
            __threadfence();
        }
    }
    __syncthreads();
}

// ---------------- prep A: zero + weight split + count + mark ----------------
__global__ __launch_bounds__(256, 8)
void k_prepA(const float* __restrict__ W0, const float* __restrict__ W1,
             const int* __restrict__ dst, const int* __restrict__ seq,
             int E, int S, int nblk) {
    const int gtid = blockIdx.x * 256 + threadIdx.x;
    const int gstride = nblk * 256;
    for (int i = gtid; i < NUM_NODES; i += gstride) {
        g_deg[i] = 0; g_fill[i] = 0; g_need[i] = 0;
    }
    if (gtid == 0) g_cnt = 0;
    for (int i = gtid; i < 2 * HIDDEN * HIDDEN; i += gstride) {
        int which = i >> 14, idx = i & 16383;   // idx = k*128+n
        float w = (which ? W1 : W0)[idx];
        int k = idx >> 7, n = idx & 127;
        __nv_bfloat16 h = __float2bfloat16(w);
        (which ? g_w1h : g_w0h)[n * 128 + k] = h;
        (which ? g_w1l : g_w0l)[n * 128 + k] = __float2bfloat16(w - __bfloat162float(h));
    }
    grid_barrier(nblk);
    for (int e = gtid; e < E; e += gstride) atomicAdd(&g_deg[dst[e]], 1);
    for (int p = gtid; p < S; p += gstride) {
        int v = seq[p];
        if (v >= 0) g_need[v] = 1;
    }
}

// ---------------- prep B: scan -> rowptr/dinv/compact list -> fill ----------------
__global__ __launch_bounds__(256, 8)
void k_prepB(const int* __restrict__ src, const int* __restrict__ dst,
             int E, int nblk, int chunk) {
    const int tid = threadIdx.x, bid = blockIdx.x;
    const int gtid = bid * 256 + tid;
    const int gstride = nblk * 256;
    __shared__ int sbuf[256];

    // P2: per-block chunk sums
    {
        int start = bid * chunk;
        int len = NUM_NODES - start;
        if (len > chunk) len = chunk;
        int acc = 0;
        for (int i = tid; i < len; i += 256) acc += g_deg[start + i];
        sbuf[tid] = acc;
        __syncthreads();
        #pragma unroll
        for (int off = 128; off > 0; off >>= 1) {
            if (tid < off) sbuf[tid] += sbuf[tid + off];
            __syncthreads();
        }
        if (tid == 0) g_blksum[bid] = sbuf[0];
    }
    grid_barrier(nblk);

    // P3: block 0 exclusive-scans chunk sums
    if (bid == 0) {
        int ele = (nblk + 255) >> 8;
        int base_i = tid * ele;
        int vals[8];
        int tsum = 0;
        for (int q = 0; q < ele && q < 8; q++) {
            int ii = base_i + q;
            vals[q] = (ii < nblk) ? g_blksum[ii] : 0;
            tsum += vals[q];
        }
        sbuf[tid] = tsum;
        __syncthreads();
        #pragma unroll
        for (int off = 1; off < 256; off <<= 1) {
            int t = (tid >= off) ? sbuf[tid - off] : 0;
            __syncthreads();
            sbuf[tid] += t;
            __syncthreads();
        }
        int run = sbuf[tid] - tsum;
        for (int q = 0; q < ele && q < 8; q++) {
            int ii = base_i + q;
            if (ii < nblk) g_blksum[ii] = run;
            run += vals[q];
        }
    }
    grid_barrier(nblk);

    // P4: chunk exclusive scan -> rowptr, dinv, compact list
    {
        int start = bid * chunk;
        int len = NUM_NODES - start;
        if (len > chunk) len = chunk;
        if (len < 0) len = 0;
        int run = (start < NUM_NODES) ? g_blksum[bid] : 0;
        for (int base = 0; base < chunk; base += 256) {
            int li = base + tid;
            int idx = start + li;
            int val = (li < len) ? g_deg[idx] : 0;
            sbuf[tid] = val;
            __syncthreads();
            #pragma unroll
            for (int off = 1; off < 256; off <<= 1) {
                int t = (tid >= off) ? sbuf[tid - off] : 0;
                __syncthreads();
                sbuf[tid] += t;
                __syncthreads();
            }
            int excl = sbuf[tid] - val;
            if (li < len) {
                g_rowptr[idx] = run + excl;
                g_dinv[idx] = rsqrtf((float)(val + 1));
                if (g_need[idx]) {
                    int s = atomicAdd(&g_cnt, 1);
                    g_slot[idx] = s;
                    g_list[s] = idx;
                }
            }
            int tot = sbuf[255];
            __syncthreads();
            run += tot;
        }
        if (gtid == 0) g_rowptr[NUM_NODES] = E;
    }
    grid_barrier(nblk);

    // P5: fill CSR
    for (int e = gtid; e < E; e += gstride) {
        int d = dst[e];
        int p = g_rowptr[d] + atomicAdd(&g_fill[d], 1);
        g_colidx[p] = src[e];
    }
}

// ---------------- bf16x3 tensor GEMM: C16[M,128] = A @ W  (split A in-smem) ----------------
#define LDS_STRIDE 136
#define TILE_HALFS (128 * LDS_STRIDE)
#define GEMM_SMEM  (4 * TILE_HALFS * 2)

template <bool FP16IN>
__global__ __launch_bounds__(256)
void k_gemm(const void* __restrict__ Av,
            const __nv_bfloat16* __restrict__ Bh, const __nv_bfloat16* __restrict__ Bl,
            __half* __restrict__ C, int M) {
    const int brow = blockIdx.x * 128;
    extern __shared__ __align__(16) __nv_bfloat16 sm[];
    __nv_bfloat16* sAh = sm;
    __nv_bfloat16* sAl = sm + TILE_HALFS;
    __nv_bfloat16* sBh = sm + 2 * TILE_HALFS;
    __nv_bfloat16* sBl = sm + 3 * TILE_HALFS;

    const int tid = threadIdx.x, wid = tid >> 5, lane = tid & 31;

    for (int i = tid; i < 2048; i += 256) {
        int r  = i >> 4;
        int c8 = (i & 15) << 3;
        int d  = r * LDS_STRIDE + c8;
        int grow = brow + r;
        float f[8];
        if (grow < M) {
            if (FP16IN) {
                const __half* A = (const __half*)Av;
                uint4 v = *reinterpret_cast<const uint4*>(A + (size_t)grow * 128 + c8);
                const __half2* hp = reinterpret_cast<const __half2*>(&v);
                #pragma unroll
                for (int q = 0; q < 4; q++) {
                    float2 fq = __half22float2(hp[q]);
                    f[q * 2] = fq.x; f[q * 2 + 1] = fq.y;
                }
            } else {
                const float* A = (const float*)Av;
                float4 a0 = *reinterpret_cast<const float4*>(A + (size_t)grow * 128 + c8);
                float4 a1 = *reinterpret_cast<const float4*>(A + (size_t)grow * 128 + c8 + 4);
                f[0] = a0.x; f[1] = a0.y; f[2] = a0.z; f[3] = a0.w;
                f[4] = a1.x; f[5] = a1.y; f[6] = a1.z; f[7] = a1.w;
            }
        } else {
            #pragma unroll
            for (int q = 0; q < 8; q++) f[q] = 0.f;
        }
        // split fp32 -> bf16 hi + lo via properly-sized staging arrays (R8 bug: UB past ushort4)
        __align__(16) unsigned short hh[8];
        __align__(16) unsigned short ll[8];
        #pragma unroll
        for (int q = 0; q < 8; q++) {
            __nv_bfloat16 hi = __float2bfloat16(f[q]);
            __nv_bfloat16 lo = __float2bfloat16(f[q] - __bfloat162float(hi));
            hh[q] = __bfloat16_as_ushort(hi);
            ll[q] = __bfloat16_as_ushort(lo);
        }
        *reinterpret_cast<ushort4*>(sAh + d)     = *reinterpret_cast<ushort4*>(hh);
        *reinterpret_cast<ushort4*>(sAh + d + 4) = *reinterpret_cast<ushort4*>(hh + 4);
        *reinterpret_cast<ushort4*>(sAl + d)     = *reinterpret_cast<ushort4*>(ll);
        *reinterpret_cast<ushort4*>(sAl + d + 4) = *reinterpret_cast<ushort4*>(ll + 4);
        *reinterpret_cast<uint4*>(sBh + d) =
            *reinterpret_cast<const uint4*>(Bh + (size_t)r * 128 + c8);
        *reinterpret_cast<uint4*>(sBl + d) =
            *reinterpret_cast<const uint4*>(Bl + (size_t)r * 128 + c8);
    }
    __syncthreads();

    const int mb = (wid & 3) * 32;
    const int nb = (wid >> 2) * 64;

    float acc[2][8][4];
    #pragma unroll
    for (int i = 0; i < 2; i++)
        #pragma unroll
        for (int j = 0; j < 8; j++)
            #pragma unroll
            for (int q = 0; q < 4; q++) acc[i][j][q] = 0.0f;

    const int lrow  = lane & 15;
    const int lbyte = (lane >> 4) << 4;

    #pragma unroll
    for (int pass = 0; pass < 3; pass++) {
        const __nv_bfloat16* pA = (pass == 1) ? sAl : sAh;
        const __nv_bfloat16* pB = (pass == 2) ? sBl : sBh;
        #pragma unroll
        for (int k16 = 0; k16 < 8; k16++) {
            int kb = k16 * 16;
            uint32_t a[2][4];
            #pragma unroll
            for (int i = 0; i < 2; i++) {
                uint32_t ad = smem_u32(pA + (mb + i * 16 + lrow) * LDS_STRIDE + kb) + lbyte;
                ldsm_x4(ad, a[i][0], a[i][1], a[i][2], a[i][3]);
            }
            uint32_t b[4][4];
            #pragma unroll
            for (int j = 0; j < 4; j++) {
                uint32_t ad = smem_u32(pB + (nb + j * 16 + lrow) * LDS_STRIDE + kb) + lbyte;
                ldsm_x4(ad, b[j][0], b[j][1], b[j][2], b[j][3]);
            }
            #pragma unroll
            for (int i = 0; i < 2; i++)
                #pragma unroll
                for (int j = 0; j < 4; j++) {
                    mma_bf16(acc[i][j * 2 + 0], a[i], b[j][0], b[j][2]);
                    mma_bf16(acc[i][j * 2 + 1], a[i], b[j][1], b[j][3]);
                }
        }
    }

    const int tr = lane >> 2, tc = (lane & 3) * 2;
    #pragma unroll
    for (int i = 0; i < 2; i++) {
        #pragma unroll
        for (int j = 0; j < 8; j++) {
            int col = nb + j * 8 + tc;
            int row0 = brow + mb + i * 16 + tr;
            if (row0 < M)
                *reinterpret_cast<__half2*>(C + (size_t)row0 * 128 + col) =
                    __floats2half2_rn(acc[i][j][0], acc[i][j][1]);
            if (row0 + 8 < M)
                *reinterpret_cast<__half2*>(C + (size_t)(row0 + 8) * 128 + col) =
                    __floats2half2_rn(acc[i][j][2], acc[i][j][3]);
        }
    }
}

// ---------------- aggregation: h[v] = act(sum norm*Y[u] + bias) ----------------
__device__ __forceinline__ float4 agg_core(const __half* __restrict__ x, int node, int lane) {
    float dv = g_dinv[node];
    float4 a  = ld_h4(x, (size_t)node * 32 + lane);
    float  ws = dv * dv;
    float4 acc = make_float4(a.x * ws, a.y * ws, a.z * ws, a.w * ws);
    int b = g_rowptr[node], e = g_rowptr[node + 1];
    for (int base = b; base < e; base += 32) {
        int m = min(32, e - base);
        int   c = 0;
        float w = 0.f;
        if (lane < m) {
            c = g_colidx[base + lane];
            w = g_dinv[c] * dv;
        }
        int j = 0;
        for (; j + 4 <= m; j += 4) {
            int   s0 = __shfl_sync(0xFFFFFFFFu, c, j);
            int   s1 = __shfl_sync(0xFFFFFFFFu, c, j + 1);
            int   s2 = __shfl_sync(0xFFFFFFFFu, c, j + 2);
            int   s3 = __shfl_sync(0xFFFFFFFFu, c, j + 3);
            float w0 = __shfl_sync(0xFFFFFFFFu, w, j);
            float w1 = __shfl_sync(0xFFFFFFFFu, w, j + 1);
            float w2 = __shfl_sync(0xFFFFFFFFu, w, j + 2);
            float w3 = __shfl_sync(0xFFFFFFFFu, w, j + 3);
            float4 v0 = ld_h4(x, (size_t)s0 * 32 + lane);
            float4 v1 = ld_h4(x, (size_t)s1 * 32 + lane);
            float4 v2 = ld_h4(x, (size_t)s2 * 32 + lane);
            float4 v3 = ld_h4(x, (size_t)s3 * 32 + lane);
            acc.x += v0.x * w0 + v1.x * w1 + v2.x * w2 + v3.x * w3;
            acc.y += v0.y * w0 + v1.y * w1 + v2.y * w2 + v3.y * w3;
            acc.z += v0.z * w0 + v1.z * w1 + v2.z * w2 + v3.z * w3;
            acc.w += v0.w * w0 + v1.w * w1 + v2.w * w2 + v3.w * w3;
        }
        for (; j < m; j++) {
            int   s0 = __shfl_sync(0xFFFFFFFFu, c, j);
            float w0 = __shfl_sync(0xFFFFFFFFu, w, j);
            float4 v0 = ld_h4(x, (size_t)s0 * 32 + lane);
            acc.x += v0.x * w0; acc.y += v0.y * w0;
            acc.z += v0.z * w0; acc.w += v0.w * w0;
        }
    }
    return acc;
}

// full: h16 = relu(A·Y0 + b0)
__global__ __launch_bounds__(256)
void k_agg(const __half* __restrict__ x, const float* __restrict__ bias,
           __half* __restrict__ out, int n) {
    int gw   = (blockIdx.x * blockDim.x + threadIdx.x) >> 5;
    int lane = threadIdx.x & 31;
    if (gw >= n) return;
    float4 acc = agg_core(x, gw, lane);
    float4 bv = *reinterpret_cast<const float4*>(bias + lane * 4);
    float o0 = fmaxf(acc.x + bv.x, 0.f), o1 = fmaxf(acc.y + bv.y, 0.f);
    float o2 = fmaxf(acc.z + bv.z, 0.f), o3 = fmaxf(acc.w + bv.w, 0.f);
    uint2 u;
    __half2 h0 = __floats2half2_rn(o0, o1);
    __half2 h1 = __floats2half2_rn(o2, o3);
    u.x = *reinterpret_cast<uint32_t*>(&h0);
    u.y = *reinterpret_cast<uint32_t*>(&h1);
    reinterpret_cast<uint2*>(out)[(size_t)gw * 32 + lane] = u;
}

// selective: z[slot] = A·Y1 + b1 (fp32, compact)
__global__ __launch_bounds__(256)
void k_agg_sel(const __half* __restrict__ x, const float* __restrict__ bias,
               float* __restrict__ out) {
    int gw   = (blockIdx.x * blockDim.x + threadIdx.x) >> 5;
    int lane = threadIdx.x & 31;
    if (gw >= g_cnt) return;
    float4 acc = agg_core(x, g_list[gw], lane);
    float4 bv = *reinterpret_cast<const float4*>(bias + lane * 4);
    float4 o = make_float4(acc.x + bv.x, acc.y + bv.y, acc.z + bv.z, acc.w + bv.w);
    reinterpret_cast<float4*>(out)[(size_t)gw * 32 + lane] = o;
}

// ---------------- final gather ----------------
__global__ __launch_bounds__(256)
void k_gather(const float* __restrict__ z, const float* __restrict__ emb,
              const int* __restrict__ seq, float* __restrict__ out, int S) {
    int t = blockIdx.x * blockDim.x + threadIdx.x;
    int pos = t >> 5, lane = t & 31;
    if (pos >= S) return;
    int v = seq[pos];
    const float4* srcp;
    size_t row;
    if (v >= 0) { srcp = reinterpret_cast<const float4*>(z);   row = (size_t)g_slot[v]; }
    else        { srcp = reinterpret_cast<const float4*>(emb); row = (size_t)(v + OFFS + NUM_NODES); }
    reinterpret_cast<float4*>(out)[(size_t)pos * 32 + lane] = srcp[row * 32 + lane];
}

// ---------------- host launch ----------------
extern "C" void kernel_launch(void* const* d_in, const int* in_sizes, int n_in,
                              void* d_out, int out_size) {
    const float* emb = (const float*)d_in[0];
    const float* W0  = (const float*)d_in[1];
    const float* b0  = (const float*)d_in[2];
    const float* W1  = (const float*)d_in[3];
    const float* b1  = (const float*)d_in[4];
    const int*   ei  = (const int*)d_in[5];
    const int*   seq = (const int*)d_in[6];

    int E = in_sizes[5] / 2;
    int S = in_sizes[6];
    const int* src = ei;
    const int* dst = ei + E;

    float *z = nullptr;
    __half *y16 = nullptr, *h16 = nullptr;
    __nv_bfloat16 *w0h = nullptr, *w0l = nullptr, *w1h = nullptr, *w1l = nullptr;
    cudaGetSymbolAddress((void**)&z,   g_z);
    cudaGetSymbolAddress((void**)&y16, g_y16);
    cudaGetSymbolAddress((void**)&h16, g_h16);
    cudaGetSymbolAddress((void**)&w0h, g_w0h);
    cudaGetSymbolAddress((void**)&w0l, g_w0l);
    cudaGetSymbolAddress((void**)&w1h, g_w1h);
    cudaGetSymbolAddress((void**)&w1l, g_w1l);

    cudaFuncSetAttribute((const void*)k_gemm<false>,
                         cudaFuncAttributeMaxDynamicSharedMemorySize, GEMM_SMEM);
    cudaFuncSetAttribute((const void*)k_gemm<true>,
                         cudaFuncAttributeMaxDynamicSharedMemorySize, GEMM_SMEM);

    int dev = 0, nsm = 0, occA = 0, occB = 0;
    cudaGetDevice(&dev);
    cudaDeviceGetAttribute(&nsm, cudaDevAttrMultiProcessorCount, dev);
    cudaOccupancyMaxActiveBlocksPerMultiprocessor(&occA, k_prepA, 256, 0);
    cudaOccupancyMaxActiveBlocksPerMultiprocessor(&occB, k_prepB, 256, 0);
    if (occA < 1) occA = 1;
    if (occB < 1) occB = 1;
    if (occA > 8) occA = 8;
    if (occB > 8) occB = 8;
    int nblkA = nsm * occA; if (nblkA > 2048) nblkA = 2048;
    int nblkB = nsm * occB; if (nblkB > 2048) nblkB = 2048;
    int chunk = (NUM_NODES + nblkB - 1) / nblkB;

    const int GEMM_GRID = (NUM_NODES + 127) / 128;

    // 0,1) prep: CSR + weight split (2 persistent kernels)
    k_prepA<<<nblkA, 256>>>(W0, W1, dst, seq, E, S, nblkA);
    k_prepB<<<nblkB, 256>>>(src, dst, E, nblkB, chunk);
    // 2) Y0 = emb @ W0 (fp32 in, fp16 out)
    k_gemm<false><<<GEMM_GRID, 256, GEMM_SMEM>>>(emb, w0h, w0l, y16, NUM_NODES);
    // 3) h = relu(A·Y0 + b0)   <-- ncu profiles launch index 3
    k_agg<<<(NUM_NODES * 32 + 255) / 256, 256>>>(y16, b0, h16, NUM_NODES);
    // 4) Y1 = h @ W1 (fp16 in, fp16 out; overwrite y16)
    k_gemm<true><<<GEMM_GRID, 256, GEMM_SMEM>>>(h16, w1h, w1l, y16, NUM_NODES);
    // 5) z = A·Y1 + b1 (needed nodes only)
    k_agg_sel<<<(MAX_SEQ * 32 + 255) / 256, 256>>>(y16, b1, z);
    // 6) gather
    k_gather<<<(S * 32 + 255) / 256, 256>>>(z, emb, seq, (float*)d_out, S);
}

// round 10
// speedup vs baseline: 1.9636x; 1.2383x over previous
#include <cuda_runtime.h>
#include <cuda_bf16.h>
#include <cuda_fp16.h>
#include <cstdint>

#define NUM_NODES 100000
#define HIDDEN    128
#define OFFS      2
#define MAX_E     1700000
#define MAX_SEQ   32768

// ---------------- device scratch ----------------
__device__ int   g_deg[NUM_NODES];
__device__ int   g_fill[NUM_NODES];
__device__ int   g_rowptr[NUM_NODES + 1];
__device__ int   g_blksum[2048];
__device__ int   g_colidx[MAX_E];
__device__ float g_dinv[NUM_NODES];
__device__ int   g_need[NUM_NODES];
__device__ int   g_slot[NUM_NODES];
__device__ int   g_list[MAX_SEQ];
__device__ int   g_cnt;
__device__ unsigned g_bar;
__device__ unsigned g_gen;
__device__ __half g_y16[(size_t)NUM_NODES * HIDDEN];   // Y0' = dinv*(emb@W0)
__device__ __half g_h16[(size_t)NUM_NODES * HIDDEN];   // h'  = dinv*relu(agg+b0)
__device__ __half g_a2[(size_t)MAX_SEQ * HIDDEN];      // compact layer-2 agg out
__device__ float  g_z[(size_t)MAX_SEQ * HIDDEN];       // compact layer-2 out
__device__ __nv_bfloat16 g_w0h[HIDDEN * HIDDEN];       // W^T [n][k] hi/lo
__device__ __nv_bfloat16 g_w0l[HIDDEN * HIDDEN];
__device__ __nv_bfloat16 g_w1h[HIDDEN * HIDDEN];
__device__ __nv_bfloat16 g_w1l[HIDDEN * HIDDEN];

// ---------------- helpers ----------------
__device__ __forceinline__ uint32_t smem_u32(const void* p) {
    uint32_t a;
    asm("{ .reg .u64 t; cvta.to.shared.u64 t, %1; cvt.u32.u64 %0, t; }" : "=r"(a) : "l"(p));
    return a;
}
__device__ __forceinline__ void ldsm_x4(uint32_t addr, uint32_t& r0, uint32_t& r1,
                                        uint32_t& r2, uint32_t& r3) {
    asm volatile("ldmatrix.sync.aligned.m8n8.x4.shared.b16 {%0,%1,%2,%3}, [%4];"
                 : "=r"(r0), "=r"(r1), "=r"(r2), "=r"(r3) : "r"(addr));
}
__device__ __forceinline__ void mma_bf16(float* c, const uint32_t* a, uint32_t b0, uint32_t b1) {
    asm volatile(
        "mma.sync.aligned.m16n8k16.row.col.f32.bf16.bf16.f32 "
        "{%0,%1,%2,%3}, {%4,%5,%6,%7}, {%8,%9}, {%0,%1,%2,%3};"
        : "+f"(c[0]), "+f"(c[1]), "+f"(c[2]), "+f"(c[3])
        : "r"(a[0]), "r"(a[1]), "r"(a[2]), "r"(a[3]), "r"(b0), "r"(b1));
}
__device__ __forceinline__ float4 ld_h4(const __half* __restrict__ x, size_t idx4) {
    uint2 u = reinterpret_cast<const uint2*>(x)[idx4];
    __half2 a = *reinterpret_cast<__half2*>(&u.x);
    __half2 b = *reinterpret_cast<__half2*>(&u.y);
    float2 fa = __half22float2(a), fb = __half22float2(b);
    return make_float4(fa.x, fa.y, fb.x, fb.y);
}
__device__ __forceinline__ void grid_barrier(int nblk) {
    __syncthreads();
    if (threadIdx.x == 0) {
        __threadfence();
        unsigned gen = *(volatile unsigned*)&g_gen;
        if (atomicAdd(&g_bar, 1u) == (unsigned)nblk - 1u) {
            atomicExch(&g_bar, 0u);
            __threadfence();
            atomicAdd(&g_gen, 1u);
        } else {
            while (*(volatile unsigned*)&g_gen == gen) { __nanosleep(64); }
            __threadfence();
        }
    }
    __syncthreads();
}

// ---------------- prep A: zero + weight split + count + mark ----------------
__global__ __launch_bounds__(256, 8)
void k_prepA(const float* __restrict__ W0, const float* __restrict__ W1,
             const int* __restrict__ dst, const int* __restrict__ seq,
             int E, int S, int nblk) {
    const int gtid = blockIdx.x * 256 + threadIdx.x;
    const int gstride = nblk * 256;
    for (int i = gtid; i < NUM_NODES; i += gstride) {
        g_deg[i] = 0; g_fill[i] = 0; g_need[i] = 0;
    }
    if (gtid == 0) g_cnt = 0;
    for (int i = gtid; i < 2 * HIDDEN * HIDDEN; i += gstride) {
        int which = i >> 14, idx = i & 16383;   // idx = k*128+n
        float w = (which ? W1 : W0)[idx];
        int k = idx >> 7, n = idx & 127;
        __nv_bfloat16 h = __float2bfloat16(w);
        (which ? g_w1h : g_w0h)[n * 128 + k] = h;
        (which ? g_w1l : g_w0l)[n * 128 + k] = __float2bfloat16(w - __bfloat162float(h));
    }
    grid_barrier(nblk);
    for (int e = gtid; e < E; e += gstride) atomicAdd(&g_deg[dst[e]], 1);
    for (int p = gtid; p < S; p += gstride) {
        int v = seq[p];
        if (v >= 0) g_need[v] = 1;
    }
}

// ---------------- prep B: scan -> rowptr/dinv/compact list -> fill ----------------
__global__ __launch_bounds__(256, 8)
void k_prepB(const int* __restrict__ src, const int* __restrict__ dst,
             int E, int nblk, int chunk) {
    const int tid = threadIdx.x, bid = blockIdx.x;
    const int gtid = bid * 256 + tid;
    const int gstride = nblk * 256;
    __shared__ int sbuf[256];

    {
        int start = bid * chunk;
        int len = NUM_NODES - start;
        if (len > chunk) len = chunk;
        int acc = 0;
        for (int i = tid; i < len; i += 256) acc += g_deg[start + i];
        sbuf[tid] = acc;
        __syncthreads();
        #pragma unroll
        for (int off = 128; off > 0; off >>= 1) {
            if (tid < off) sbuf[tid] += sbuf[tid + off];
            __syncthreads();
        }
        if (tid == 0) g_blksum[bid] = sbuf[0];
    }
    grid_barrier(nblk);

    if (bid == 0) {
        int ele = (nblk + 255) >> 8;
        int base_i = tid * ele;
        int vals[8];
        int tsum = 0;
        for (int q = 0; q < ele && q < 8; q++) {
            int ii = base_i + q;
            vals[q] = (ii < nblk) ? g_blksum[ii] : 0;
            tsum += vals[q];
        }
        sbuf[tid] = tsum;
        __syncthreads();
        #pragma unroll
        for (int off = 1; off < 256; off <<= 1) {
            int t = (tid >= off) ? sbuf[tid - off] : 0;
            __syncthreads();
            sbuf[tid] += t;
            __syncthreads();
        }
        int run = sbuf[tid] - tsum;
        for (int q = 0; q < ele && q < 8; q++) {
            int ii = base_i + q;
            if (ii < nblk) g_blksum[ii] = run;
            run += vals[q];
        }
    }
    grid_barrier(nblk);

    {
        int start = bid * chunk;
        int len = NUM_NODES - start;
        if (len > chunk) len = chunk;
        if (len < 0) len = 0;
        int run = (start < NUM_NODES) ? g_blksum[bid] : 0;
        for (int base = 0; base < chunk; base += 256) {
            int li = base + tid;
            int idx = start + li;
            int val = (li < len) ? g_deg[idx] : 0;
            sbuf[tid] = val;
            __syncthreads();
            #pragma unroll
            for (int off = 1; off < 256; off <<= 1) {
                int t = (tid >= off) ? sbuf[tid - off] : 0;
                __syncthreads();
                sbuf[tid] += t;
                __syncthreads();
            }
            int excl = sbuf[tid] - val;
            if (li < len) {
                g_rowptr[idx] = run + excl;
                g_dinv[idx] = rsqrtf((float)(val + 1));
                if (g_need[idx]) {
                    int s = atomicAdd(&g_cnt, 1);
                    g_slot[idx] = s;
                    g_list[s] = idx;
                }
            }
            int tot = sbuf[255];
            __syncthreads();
            run += tot;
        }
        if (gtid == 0) g_rowptr[NUM_NODES] = E;
    }
    grid_barrier(nblk);

    for (int e = gtid; e < E; e += gstride) {
        int d = dst[e];
        int p = g_rowptr[d] + atomicAdd(&g_fill[d], 1);
        g_colidx[p] = src[e];
    }
}

// ---------------- bf16x3 tensor GEMM (split A in-smem) ----------------
// FP16IN: A rows fp16; SCALED: fp16-out rows scaled by dinv[row];
// COMPACT: M = g_cnt; FOUT: fp32 out + bias.
#define LDS_STRIDE 136
#define TILE_HALFS (128 * LDS_STRIDE)
#define GEMM_SMEM  (4 * TILE_HALFS * 2)

template <bool FP16IN, bool SCALED, bool COMPACT, bool FOUT>
__global__ __launch_bounds__(256)
void k_gemm(const void* __restrict__ Av,
            const __nv_bfloat16* __restrict__ Bh, const __nv_bfloat16* __restrict__ Bl,
            const float* __restrict__ bias, void* __restrict__ Cv, int Mfix) {
    const int M = COMPACT ? g_cnt : Mfix;
    const int brow = blockIdx.x * 128;
    if (brow >= M) return;

    extern __shared__ __align__(16) __nv_bfloat16 sm[];
    __nv_bfloat16* sAh = sm;
    __nv_bfloat16* sAl = sm + TILE_HALFS;
    __nv_bfloat16* sBh = sm + 2 * TILE_HALFS;
    __nv_bfloat16* sBl = sm + 3 * TILE_HALFS;

    const int tid = threadIdx.x, wid = tid >> 5, lane = tid & 31;

    for (int i = tid; i < 2048; i += 256) {
        int r  = i >> 4;
        int c8 = (i & 15) << 3;
        int d  = r * LDS_STRIDE + c8;
        int grow = brow + r;
        float f[8];
        if (grow < M) {
            if (FP16IN) {
                const __half* A = (const __half*)Av;
                uint4 v = *reinterpret_cast<const uint4*>(A + (size_t)grow * 128 + c8);
                const __half2* hp = reinterpret_cast<const __half2*>(&v);
                #pragma unroll
                for (int q = 0; q < 4; q++) {
                    float2 fq = __half22float2(hp[q]);
                    f[q * 2] = fq.x; f[q * 2 + 1] = fq.y;
                }
            } else {
                const float* A = (const float*)Av;
                float4 a0 = *reinterpret_cast<const float4*>(A + (size_t)grow * 128 + c8);
                float4 a1 = *reinterpret_cast<const float4*>(A + (size_t)grow * 128 + c8 + 4);
                f[0] = a0.x; f[1] = a0.y; f[2] = a0.z; f[3] = a0.w;
                f[4] = a1.x; f[5] = a1.y; f[6] = a1.z; f[7] = a1.w;
            }
        } else {
            #pragma unroll
            for (int q = 0; q < 8; q++) f[q] = 0.f;
        }
        __align__(16) unsigned short hh[8];
        __align__(16) unsigned short ll[8];
        #pragma unroll
        for (int q = 0; q < 8; q++) {
            __nv_bfloat16 hi = __float2bfloat16(f[q]);
            __nv_bfloat16 lo = __float2bfloat16(f[q] - __bfloat162float(hi));
            hh[q] = __bfloat16_as_ushort(hi);
            ll[q] = __bfloat16_as_ushort(lo);
        }
        *reinterpret_cast<ushort4*>(sAh + d)     = *reinterpret_cast<ushort4*>(hh);
        *reinterpret_cast<ushort4*>(sAh + d + 4) = *reinterpret_cast<ushort4*>(hh + 4);
        *reinterpret_cast<ushort4*>(sAl + d)     = *reinterpret_cast<ushort4*>(ll);
        *reinterpret_cast<ushort4*>(sAl + d + 4) = *reinterpret_cast<ushort4*>(ll + 4);
        *reinterpret_cast<uint4*>(sBh + d) =
            *reinterpret_cast<const uint4*>(Bh + (size_t)r * 128 + c8);
        *reinterpret_cast<uint4*>(sBl + d) =
            *reinterpret_cast<const uint4*>(Bl + (size_t)r * 128 + c8);
    }
    __syncthreads();

    const int mb = (wid & 3) * 32;
    const int nb = (wid >> 2) * 64;

    float acc[2][8][4];
    #pragma unroll
    for (int i = 0; i < 2; i++)
        #pragma unroll
        for (int j = 0; j < 8; j++)
            #pragma unroll
            for (int q = 0; q < 4; q++) acc[i][j][q] = 0.0f;

    const int lrow  = lane & 15;
    const int lbyte = (lane >> 4) << 4;

    #pragma unroll
    for (int pass = 0; pass < 3; pass++) {
        const __nv_bfloat16* pA = (pass == 1) ? sAl : sAh;
        const __nv_bfloat16* pB = (pass == 2) ? sBl : sBh;
        #pragma unroll
        for (int k16 = 0; k16 < 8; k16++) {
            int kb = k16 * 16;
            uint32_t a[2][4];
            #pragma unroll
            for (int i = 0; i < 2; i++) {
                uint32_t ad = smem_u32(pA + (mb + i * 16 + lrow) * LDS_STRIDE + kb) + lbyte;
                ldsm_x4(ad, a[i][0], a[i][1], a[i][2], a[i][3]);
            }
            uint32_t b[4][4];
            #pragma unroll
            for (int j = 0; j < 4; j++) {
                uint32_t ad = smem_u32(pB + (nb + j * 16 + lrow) * LDS_STRIDE + kb) + lbyte;
                ldsm_x4(ad, b[j][0], b[j][1], b[j][2], b[j][3]);
            }
            #pragma unroll
            for (int i = 0; i < 2; i++)
                #pragma unroll
                for (int j = 0; j < 4; j++) {
                    mma_bf16(acc[i][j * 2 + 0], a[i], b[j][0], b[j][2]);
                    mma_bf16(acc[i][j * 2 + 1], a[i], b[j][1], b[j][3]);
                }
        }
    }

    const int tr = lane >> 2, tc = (lane & 3) * 2;
    #pragma unroll
    for (int i = 0; i < 2; i++) {
        int row0 = brow + mb + i * 16 + tr;
        float s0 = 1.f, s1 = 1.f;
        if (SCALED) {
            if (row0 < M)     s0 = g_dinv[row0];
            if (row0 + 8 < M) s1 = g_dinv[row0 + 8];
        }
        #pragma unroll
        for (int j = 0; j < 8; j++) {
            int col = nb + j * 8 + tc;
            if (FOUT) {
                float* C = (float*)Cv;
                float bx = bias[col], by = bias[col + 1];
                if (row0 < M) {
                    float2 o = make_float2(acc[i][j][0] + bx, acc[i][j][1] + by);
                    *reinterpret_cast<float2*>(C + (size_t)row0 * 128 + col) = o;
                }
                if (row0 + 8 < M) {
                    float2 o = make_float2(acc[i][j][2] + bx, acc[i][j][3] + by);
                    *reinterpret_cast<float2*>(C + (size_t)(row0 + 8) * 128 + col) = o;
                }
            } else {
                __half* C = (__half*)Cv;
                if (row0 < M)
                    *reinterpret_cast<__half2*>(C + (size_t)row0 * 128 + col) =
                        __floats2half2_rn(acc[i][j][0] * s0, acc[i][j][1] * s0);
                if (row0 + 8 < M)
                    *reinterpret_cast<__half2*>(C + (size_t)(row0 + 8) * 128 + col) =
                        __floats2half2_rn(acc[i][j][2] * s1, acc[i][j][3] * s1);
            }
        }
    }
}

// ---------------- weightless aggregation (rows pre-scaled by dinv) ----------------
__device__ __forceinline__ float4 agg_core(const __half* __restrict__ x, int node, int lane) {
    float4 acc = ld_h4(x, (size_t)node * 32 + lane);   // self term (pre-scaled)
    int b = g_rowptr[node], e = g_rowptr[node + 1];
    for (int base = b; base < e; base += 32) {
        int m = min(32, e - base);
        int c = (lane < m) ? g_colidx[base + lane] : 0;
        int j = 0;
        for (; j + 4 <= m; j += 4) {
            int s0 = __shfl_sync(0xFFFFFFFFu, c, j);
            int s1 = __shfl_sync(0xFFFFFFFFu, c, j + 1);
            int s2 = __shfl_sync(0xFFFFFFFFu, c, j + 2);
            int s3 = __shfl_sync(0xFFFFFFFFu, c, j + 3);
            float4 v0 = ld_h4(x, (size_t)s0 * 32 + lane);
            float4 v1 = ld_h4(x, (size_t)s1 * 32 + lane);
            float4 v2 = ld_h4(x, (size_t)s2 * 32 + lane);
            float4 v3 = ld_h4(x, (size_t)s3 * 32 + lane);
            acc.x += v0.x + v1.x + v2.x + v3.x;
            acc.y += v0.y + v1.y + v2.y + v3.y;
            acc.z += v0.z + v1.z + v2.z + v3.z;
            acc.w += v0.w + v1.w + v2.w + v3.w;
        }
        for (; j < m; j++) {
            int s0 = __shfl_sync(0xFFFFFFFFu, c, j);
            float4 v0 = ld_h4(x, (size_t)s0 * 32 + lane);
            acc.x += v0.x; acc.y += v0.y; acc.z += v0.z; acc.w += v0.w;
        }
    }
    return acc;
}

// layer-1 agg: h'[v] = dinv[v] * relu(dinv[v]*acc + b0)
__global__ __launch_bounds__(256)
void k_agg(const __half* __restrict__ x, const float* __restrict__ bias,
           __half* __restrict__ out, int n) {
    int gw   = (blockIdx.x * blockDim.x + threadIdx.x) >> 5;
    int lane = threadIdx.x & 31;
    if (gw >= n) return;
    float4 acc = agg_core(x, gw, lane);
    float dv = g_dinv[gw];
    float4 bv = *reinterpret_cast<const float4*>(bias + lane * 4);
    float o0 = fmaxf(fmaf(acc.x, dv, bv.x), 0.f) * dv;
    float o1 = fmaxf(fmaf(acc.y, dv, bv.y), 0.f) * dv;
    float o2 = fmaxf(fmaf(acc.z, dv, bv.z), 0.f) * dv;
    float o3 = fmaxf(fmaf(acc.w, dv, bv.w), 0.f) * dv;
    uint2 u;
    __half2 h0 = __floats2half2_rn(o0, o1);
    __half2 h1 = __floats2half2_rn(o2, o3);
    u.x = *reinterpret_cast<uint32_t*>(&h0);
    u.y = *reinterpret_cast<uint32_t*>(&h1);
    reinterpret_cast<uint2*>(out)[(size_t)gw * 32 + lane] = u;
}

// layer-2 agg (compact): a2[slot] = dinv[v] * acc  (fp16)
__global__ __launch_bounds__(256)
void k_agg_sel(const __half* __restrict__ x, __half* __restrict__ out) {
    int gw   = (blockIdx.x * blockDim.x + threadIdx.x) >> 5;
    int lane = threadIdx.x & 31;
    if (gw >= g_cnt) return;
    int node = g_list[gw];
    float4 acc = agg_core(x, node, lane);
    float dv = g_dinv[node];
    uint2 u;
    __half2 h0 = __floats2half2_rn(acc.x * dv, acc.y * dv);
    __half2 h1 = __floats2half2_rn(acc.z * dv, acc.w * dv);
    u.x = *reinterpret_cast<uint32_t*>(&h0);
    u.y = *reinterpret_cast<uint32_t*>(&h1);
    reinterpret_cast<uint2*>(out)[(size_t)gw * 32 + lane] = u;
}

// ---------------- final gather ----------------
__global__ __launch_bounds__(256)
void k_gather(const float* __restrict__ z, const float* __restrict__ emb,
              const int* __restrict__ seq, float* __restrict__ out, int S) {
    int t = blockIdx.x * blockDim.x + threadIdx.x;
    int pos = t >> 5, lane = t & 31;
    if (pos >= S) return;
    int v = seq[pos];
    const float4* srcp;
    size_t row;
    if (v >= 0) { srcp = reinterpret_cast<const float4*>(z);   row = (size_t)g_slot[v]; }
    else        { srcp = reinterpret_cast<const float4*>(emb); row = (size_t)(v + OFFS + NUM_NODES); }
    reinterpret_cast<float4*>(out)[(size_t)pos * 32 + lane] = srcp[row * 32 + lane];
}

// ---------------- host launch ----------------
extern "C" void kernel_launch(void* const* d_in, const int* in_sizes, int n_in,
                              void* d_out, int out_size) {
    const float* emb = (const float*)d_in[0];
    const float* W0  = (const float*)d_in[1];
    const float* b0  = (const float*)d_in[2];
    const float* W1  = (const float*)d_in[3];
    const float* b1  = (const float*)d_in[4];
    const int*   ei  = (const int*)d_in[5];
    const int*   seq = (const int*)d_in[6];

    int E = in_sizes[5] / 2;
    int S = in_sizes[6];
    const int* src = ei;
    const int* dst = ei + E;

    float *z = nullptr;
    __half *y16 = nullptr, *h16 = nullptr, *a2 = nullptr;
    __nv_bfloat16 *w0h = nullptr, *w0l = nullptr, *w1h = nullptr, *w1l = nullptr;
    cudaGetSymbolAddress((void**)&z,   g_z);
    cudaGetSymbolAddress((void**)&y16, g_y16);
    cudaGetSymbolAddress((void**)&h16, g_h16);
    cudaGetSymbolAddress((void**)&a2,  g_a2);
    cudaGetSymbolAddress((void**)&w0h, g_w0h);
    cudaGetSymbolAddress((void**)&w0l, g_w0l);
    cudaGetSymbolAddress((void**)&w1h, g_w1h);
    cudaGetSymbolAddress((void**)&w1l, g_w1l);

    cudaFuncSetAttribute((const void*)k_gemm<false, true, false, false>,
                         cudaFuncAttributeMaxDynamicSharedMemorySize, GEMM_SMEM);
    cudaFuncSetAttribute((const void*)k_gemm<true, false, true, true>,
                         cudaFuncAttributeMaxDynamicSharedMemorySize, GEMM_SMEM);

    int dev = 0, nsm = 0, occA = 0, occB = 0;
    cudaGetDevice(&dev);
    cudaDeviceGetAttribute(&nsm, cudaDevAttrMultiProcessorCount, dev);
    cudaOccupancyMaxActiveBlocksPerMultiprocessor(&occA, k_prepA, 256, 0);
    cudaOccupancyMaxActiveBlocksPerMultiprocessor(&occB, k_prepB, 256, 0);
    if (occA < 1) occA = 1;
    if (occB < 1) occB = 1;
    if (occA > 8) occA = 8;
    if (occB > 8) occB = 8;
    int nblkA = nsm * occA; if (nblkA > 2048) nblkA = 2048;
    int nblkB = nsm * occB; if (nblkB > 2048) nblkB = 2048;
    int chunk = (NUM_NODES + nblkB - 1) / nblkB;

    // 0,1) prep
    k_prepA<<<nblkA, 256>>>(W0, W1, dst, seq, E, S, nblkA);
    k_prepB<<<nblkB, 256>>>(src, dst, E, nblkB, chunk);
    // 2) Y0' = dinv * (emb @ W0)    (fp32 in, scaled fp16 out)
    k_gemm<false, true, false, false><<<(NUM_NODES + 127) / 128, 256, GEMM_SMEM>>>(
        emb, w0h, w0l, nullptr, y16, NUM_NODES);
    // 3) h' = dinv * relu(agg(Y0') + b0)    <-- ncu index 3
    k_agg<<<(NUM_NODES * 32 + 255) / 256, 256>>>(y16, b0, h16, NUM_NODES);
    // 4) a2 = agg_sel(h')  (compact, fp16)
    k_agg_sel<<<(MAX_SEQ * 32 + 255) / 256, 256>>>(h16, a2);
    // 5) z = a2 @ W1 + b1  (compact, fp32 out)
    k_gemm<true, false, true, true><<<(MAX_SEQ + 127) / 128, 256, GEMM_SMEM>>>(
        a2, w1h, w1l, b1, z, 0);
    // 6) gather
    k_gather<<<(S * 32 + 255) / 256, 256>>>(z, emb, seq, (float*)d_out, S);
}

// round 11
// speedup vs baseline: 2.0017x; 1.0194x over previous
#include <cuda_runtime.h>
#include <cuda_bf16.h>
#include <cuda_fp16.h>
#include <cstdint>

#define NUM_NODES 100000
#define HIDDEN    128
#define OFFS      2
#define MAX_E     1700000
#define MAX_SEQ   32768

// ---------------- device scratch ----------------
__device__ int   g_deg[NUM_NODES];
__device__ int   g_fill[NUM_NODES];
__device__ int   g_rowptr[NUM_NODES + 1];
__device__ int   g_blksum[2048];
__device__ int   g_colidx[MAX_E];
__device__ float g_dinv[NUM_NODES];
__device__ int   g_need[NUM_NODES];
__device__ int   g_slot[NUM_NODES];
__device__ int   g_list[MAX_SEQ];
__device__ int   g_cnt;
__device__ unsigned g_bar;
__device__ unsigned g_gen;
__device__ __half g_y16[(size_t)NUM_NODES * HIDDEN];   // Y0' = dinv*(emb@W0)
__device__ __half g_h16[(size_t)NUM_NODES * HIDDEN];   // h'  = dinv*relu(agg+b0)
__device__ __half g_a2[(size_t)MAX_SEQ * HIDDEN];      // compact layer-2 agg out
__device__ float  g_z[(size_t)MAX_SEQ * HIDDEN];       // compact layer-2 out
__device__ __nv_bfloat16 g_w0h[HIDDEN * HIDDEN];       // W^T [n][k] hi/lo
__device__ __nv_bfloat16 g_w0l[HIDDEN * HIDDEN];
__device__ __nv_bfloat16 g_w1h[HIDDEN * HIDDEN];
__device__ __nv_bfloat16 g_w1l[HIDDEN * HIDDEN];

// ---------------- helpers ----------------
__device__ __forceinline__ uint32_t smem_u32(const void* p) {
    uint32_t a;
    asm("{ .reg .u64 t; cvta.to.shared.u64 t, %1; cvt.u32.u64 %0, t; }" : "=r"(a) : "l"(p));
    return a;
}
__device__ __forceinline__ void ldsm_x4(uint32_t addr, uint32_t& r0, uint32_t& r1,
                                        uint32_t& r2, uint32_t& r3) {
    asm volatile("ldmatrix.sync.aligned.m8n8.x4.shared.b16 {%0,%1,%2,%3}, [%4];"
                 : "=r"(r0), "=r"(r1), "=r"(r2), "=r"(r3) : "r"(addr));
}
__device__ __forceinline__ void mma_bf16(float* c, const uint32_t* a, uint32_t b0, uint32_t b1) {
    asm volatile(
        "mma.sync.aligned.m16n8k16.row.col.f32.bf16.bf16.f32 "
        "{%0,%1,%2,%3}, {%4,%5,%6,%7}, {%8,%9}, {%0,%1,%2,%3};"
        : "+f"(c[0]), "+f"(c[1]), "+f"(c[2]), "+f"(c[3])
        : "r"(a[0]), "r"(a[1]), "r"(a[2]), "r"(a[3]), "r"(b0), "r"(b1));
}
__device__ __forceinline__ float4 ld_h4(const __half* __restrict__ x, size_t idx4) {
    uint2 u = reinterpret_cast<const uint2*>(x)[idx4];
    __half2 a = *reinterpret_cast<__half2*>(&u.x);
    __half2 b = *reinterpret_cast<__half2*>(&u.y);
    float2 fa = __half22float2(a), fb = __half22float2(b);
    return make_float4(fa.x, fa.y, fb.x, fb.y);
}
__device__ __forceinline__ void grid_barrier(int nblk) {
    __syncthreads();
    if (threadIdx.x == 0) {
        __threadfence();
        unsigned gen = *(volatile unsigned*)&g_gen;
        if (atomicAdd(&g_bar, 1u) == (unsigned)nblk - 1u) {
            atomicExch(&g_bar, 0u);
            __threadfence();
            atomicAdd(&g_gen, 1u);
        } else {
            while (*(volatile unsigned*)&g_gen == gen) { __nanosleep(64); }
            __threadfence();
        }
    }
    __syncthreads();
}

// ---------------- persistent prep: all CSR/prep phases in ONE kernel ----------------
__global__ __launch_bounds__(256, 8)
void k_prep(const float* __restrict__ W0, const float* __restrict__ W1,
            const int* __restrict__ src, const int* __restrict__ dst,
            const int* __restrict__ seq, int E, int S, int nblk, int chunk) {
    const int tid = threadIdx.x, bid = blockIdx.x;
    const int gtid = bid * 256 + tid;
    const int gstride = nblk * 256;
    __shared__ int sbuf[256];

    // P0: zero counters + weight split
    for (int i = gtid; i < NUM_NODES; i += gstride) {
        g_deg[i] = 0; g_fill[i] = 0; g_need[i] = 0;
    }
    if (gtid == 0) g_cnt = 0;
    for (int i = gtid; i < 2 * HIDDEN * HIDDEN; i += gstride) {
        int which = i >> 14, idx = i & 16383;   // idx = k*128+n
        float w = (which ? W1 : W0)[idx];
        int k = idx >> 7, n = idx & 127;
        __nv_bfloat16 h = __float2bfloat16(w);
        (which ? g_w1h : g_w0h)[n * 128 + k] = h;
        (which ? g_w1l : g_w0l)[n * 128 + k] = __float2bfloat16(w - __bfloat162float(h));
    }
    grid_barrier(nblk);

    // P1: degree count + mark needed
    for (int e = gtid; e < E; e += gstride) atomicAdd(&g_deg[dst[e]], 1);
    for (int p = gtid; p < S; p += gstride) {
        int v = seq[p];
        if (v >= 0) g_need[v] = 1;
    }
    grid_barrier(nblk);

    // P2: per-block chunk sums
    {
        int start = bid * chunk;
        int len = NUM_NODES - start;
        if (len > chunk) len = chunk;
        int acc = 0;
        for (int i = tid; i < len; i += 256) acc += g_deg[start + i];
        sbuf[tid] = acc;
        __syncthreads();
        #pragma unroll
        for (int off = 128; off > 0; off >>= 1) {
            if (tid < off) sbuf[tid] += sbuf[tid + off];
            __syncthreads();
        }
        if (tid == 0) g_blksum[bid] = sbuf[0];
    }
    grid_barrier(nblk);

    // P3: block 0 exclusive-scans chunk sums
    if (bid == 0) {
        int ele = (nblk + 255) >> 8;
        int base_i = tid * ele;
        int vals[8];
        int tsum = 0;
        for (int q = 0; q < ele && q < 8; q++) {
            int ii = base_i + q;
            vals[q] = (ii < nblk) ? g_blksum[ii] : 0;
            tsum += vals[q];
        }
        sbuf[tid] = tsum;
        __syncthreads();
        #pragma unroll
        for (int off = 1; off < 256; off <<= 1) {
            int t = (tid >= off) ? sbuf[tid - off] : 0;
            __syncthreads();
            sbuf[tid] += t;
            __syncthreads();
        }
        int run = sbuf[tid] - tsum;
        for (int q = 0; q < ele && q < 8; q++) {
            int ii = base_i + q;
            if (ii < nblk) g_blksum[ii] = run;
            run += vals[q];
        }
    }
    grid_barrier(nblk);

    // P4: chunk exclusive scan -> rowptr, dinv, compact list
    {
        int start = bid * chunk;
        int len = NUM_NODES - start;
        if (len > chunk) len = chunk;
        if (len < 0) len = 0;
        int run = (start < NUM_NODES) ? g_blksum[bid] : 0;
        for (int base = 0; base < chunk; base += 256) {
            int li = base + tid;
            int idx = start + li;
            int val = (li < len) ? g_deg[idx] : 0;
            sbuf[tid] = val;
            __syncthreads();
            #pragma unroll
            for (int off = 1; off < 256; off <<= 1) {
                int t = (tid >= off) ? sbuf[tid - off] : 0;
                __syncthreads();
                sbuf[tid] += t;
                __syncthreads();
            }
            int excl = sbuf[tid] - val;
            if (li < len) {
                g_rowptr[idx] = run + excl;
                g_dinv[idx] = rsqrtf((float)(val + 1));
                if (g_need[idx]) {
                    int s = atomicAdd(&g_cnt, 1);
                    g_slot[idx] = s;
                    g_list[s] = idx;
                }
            }
            int tot = sbuf[255];
            __syncthreads();
            run += tot;
        }
        if (gtid == 0) g_rowptr[NUM_NODES] = E;
    }
    grid_barrier(nblk);

    // P5: fill CSR
    for (int e = gtid; e < E; e += gstride) {
        int d = dst[e];
        int p = g_rowptr[d] + atomicAdd(&g_fill[d], 1);
        g_colidx[p] = src[e];
    }
}

// ---------------- bf16x3 tensor GEMM (split A in-smem) ----------------
#define LDS_STRIDE 136
#define TILE_HALFS (128 * LDS_STRIDE)
#define GEMM_SMEM  (4 * TILE_HALFS * 2)

template <bool FP16IN, bool SCALED, bool COMPACT, bool FOUT>
__global__ __launch_bounds__(256)
void k_gemm(const void* __restrict__ Av,
            const __nv_bfloat16* __restrict__ Bh, const __nv_bfloat16* __restrict__ Bl,
            const float* __restrict__ bias, void* __restrict__ Cv, int Mfix) {
    const int M = COMPACT ? g_cnt : Mfix;
    const int brow = blockIdx.x * 128;
    if (brow >= M) return;

    extern __shared__ __align__(16) __nv_bfloat16 sm[];
    __nv_bfloat16* sAh = sm;
    __nv_bfloat16* sAl = sm + TILE_HALFS;
    __nv_bfloat16* sBh = sm + 2 * TILE_HALFS;
    __nv_bfloat16* sBl = sm + 3 * TILE_HALFS;

    const int tid = threadIdx.x, wid = tid >> 5, lane = tid & 31;

    for (int i = tid; i < 2048; i += 256) {
        int r  = i >> 4;
        int c8 = (i & 15) << 3;
        int d  = r * LDS_STRIDE + c8;
        int grow = brow + r;
        float f[8];
        if (grow < M) {
            if (FP16IN) {
                const __half* A = (const __half*)Av;
                uint4 v = *reinterpret_cast<const uint4*>(A + (size_t)grow * 128 + c8);
                const __half2* hp = reinterpret_cast<const __half2*>(&v);
                #pragma unroll
                for (int q = 0; q < 4; q++) {
                    float2 fq = __half22float2(hp[q]);
                    f[q * 2] = fq.x; f[q * 2 + 1] = fq.y;
                }
            } else {
                const float* A = (const float*)Av;
                float4 a0 = *reinterpret_cast<const float4*>(A + (size_t)grow * 128 + c8);
                float4 a1 = *reinterpret_cast<const float4*>(A + (size_t)grow * 128 + c8 + 4);
                f[0] = a0.x; f[1] = a0.y; f[2] = a0.z; f[3] = a0.w;
                f[4] = a1.x; f[5] = a1.y; f[6] = a1.z; f[7] = a1.w;
            }
        } else {
            #pragma unroll
            for (int q = 0; q < 8; q++) f[q] = 0.f;
        }
        __align__(16) unsigned short hh[8];
        __align__(16) unsigned short ll[8];
        #pragma unroll
        for (int q = 0; q < 8; q++) {
            __nv_bfloat16 hi = __float2bfloat16(f[q]);
            __nv_bfloat16 lo = __float2bfloat16(f[q] - __bfloat162float(hi));
            hh[q] = __bfloat16_as_ushort(hi);
            ll[q] = __bfloat16_as_ushort(lo);
        }
        *reinterpret_cast<ushort4*>(sAh + d)     = *reinterpret_cast<ushort4*>(hh);
        *reinterpret_cast<ushort4*>(sAh + d + 4) = *reinterpret_cast<ushort4*>(hh + 4);
        *reinterpret_cast<ushort4*>(sAl + d)     = *reinterpret_cast<ushort4*>(ll);
        *reinterpret_cast<ushort4*>(sAl + d + 4) = *reinterpret_cast<ushort4*>(ll + 4);
        *reinterpret_cast<uint4*>(sBh + d) =
            *reinterpret_cast<const uint4*>(Bh + (size_t)r * 128 + c8);
        *reinterpret_cast<uint4*>(sBl + d) =
            *reinterpret_cast<const uint4*>(Bl + (size_t)r * 128 + c8);
    }
    __syncthreads();

    const int mb = (wid & 3) * 32;
    const int nb = (wid >> 2) * 64;

    float acc[2][8][4];
    #pragma unroll
    for (int i = 0; i < 2; i++)
        #pragma unroll
        for (int j = 0; j < 8; j++)
            #pragma unroll
            for (int q = 0; q < 4; q++) acc[i][j][q] = 0.0f;

    const int lrow  = lane & 15;
    const int lbyte = (lane >> 4) << 4;

    #pragma unroll
    for (int pass = 0; pass < 3; pass++) {
        const __nv_bfloat16* pA = (pass == 1) ? sAl : sAh;
        const __nv_bfloat16* pB = (pass == 2) ? sBl : sBh;
        #pragma unroll
        for (int k16 = 0; k16 < 8; k16++) {
            int kb = k16 * 16;
            uint32_t a[2][4];
            #pragma unroll
            for (int i = 0; i < 2; i++) {
                uint32_t ad = smem_u32(pA + (mb + i * 16 + lrow) * LDS_STRIDE + kb) + lbyte;
                ldsm_x4(ad, a[i][0], a[i][1], a[i][2], a[i][3]);
            }
            uint32_t b[4][4];
            #pragma unroll
            for (int j = 0; j < 4; j++) {
                uint32_t ad = smem_u32(pB + (nb + j * 16 + lrow) * LDS_STRIDE + kb) + lbyte;
                ldsm_x4(ad, b[j][0], b[j][1], b[j][2], b[j][3]);
            }
            #pragma unroll
            for (int i = 0; i < 2; i++)
                #pragma unroll
                for (int j = 0; j < 4; j++) {
                    mma_bf16(acc[i][j * 2 + 0], a[i], b[j][0], b[j][2]);
                    mma_bf16(acc[i][j * 2 + 1], a[i], b[j][1], b[j][3]);
                }
        }
    }

    const int tr = lane >> 2, tc = (lane & 3) * 2;
    #pragma unroll
    for (int i = 0; i < 2; i++) {
        int row0 = brow + mb + i * 16 + tr;
        float s0 = 1.f, s1 = 1.f;
        if (SCALED) {
            if (row0 < M)     s0 = g_dinv[row0];
            if (row0 + 8 < M) s1 = g_dinv[row0 + 8];
        }
        #pragma unroll
        for (int j = 0; j < 8; j++) {
            int col = nb + j * 8 + tc;
            if (FOUT) {
                float* C = (float*)Cv;
                float bx = bias[col], by = bias[col + 1];
                if (row0 < M) {
                    float2 o = make_float2(acc[i][j][0] + bx, acc[i][j][1] + by);
                    *reinterpret_cast<float2*>(C + (size_t)row0 * 128 + col) = o;
                }
                if (row0 + 8 < M) {
                    float2 o = make_float2(acc[i][j][2] + bx, acc[i][j][3] + by);
                    *reinterpret_cast<float2*>(C + (size_t)(row0 + 8) * 128 + col) = o;
                }
            } else {
                __half* C = (__half*)Cv;
                if (row0 < M)
                    *reinterpret_cast<__half2*>(C + (size_t)row0 * 128 + col) =
                        __floats2half2_rn(acc[i][j][0] * s0, acc[i][j][1] * s0);
                if (row0 + 8 < M)
                    *reinterpret_cast<__half2*>(C + (size_t)(row0 + 8) * 128 + col) =
                        __floats2half2_rn(acc[i][j][2] * s1, acc[i][j][3] * s1);
            }
        }
    }
}

// ---------------- weightless aggregation with fp16 pairwise pre-reduction ----------------
__device__ __forceinline__ float4 agg_core(const __half* __restrict__ x, int node, int lane) {
    float4 acc = ld_h4(x, (size_t)node * 32 + lane);   // self term (pre-scaled)
    const uint2* xr = reinterpret_cast<const uint2*>(x);
    int b = g_rowptr[node], e = g_rowptr[node + 1];
    for (int base = b; base < e; base += 32) {
        int m = min(32, e - base);
        int c = (lane < m) ? g_colidx[base + lane] : 0;
        int j = 0;
        for (; j + 4 <= m; j += 4) {
            int s0 = __shfl_sync(0xFFFFFFFFu, c, j);
            int s1 = __shfl_sync(0xFFFFFFFFu, c, j + 1);
            int s2 = __shfl_sync(0xFFFFFFFFu, c, j + 2);
            int s3 = __shfl_sync(0xFFFFFFFFu, c, j + 3);
            uint2 u0 = xr[(size_t)s0 * 32 + lane];
            uint2 u1 = xr[(size_t)s1 * 32 + lane];
            uint2 u2 = xr[(size_t)s2 * 32 + lane];
            uint2 u3 = xr[(size_t)s3 * 32 + lane];
            // one fp16 pairing level (halves CVT+FADD count)
            __half2 p0 = __hadd2(*reinterpret_cast<__half2*>(&u0.x),
                                 *reinterpret_cast<__half2*>(&u1.x));
            __half2 p1 = __hadd2(*reinterpret_cast<__half2*>(&u0.y),
                                 *reinterpret_cast<__half2*>(&u1.y));
            __half2 q0 = __hadd2(*reinterpret_cast<__half2*>(&u2.x),
                                 *reinterpret_cast<__half2*>(&u3.x));
            __half2 q1 = __hadd2(*reinterpret_cast<__half2*>(&u2.y),
                                 *reinterpret_cast<__half2*>(&u3.y));
            float2 f0 = __half22float2(p0), f1 = __half22float2(p1);
            float2 g0 = __half22float2(q0), g1 = __half22float2(q1);
            acc.x += f0.x + g0.x;
            acc.y += f0.y + g0.y;
            acc.z += f1.x + g1.x;
            acc.w += f1.y + g1.y;
        }
        for (; j < m; j++) {
            int s0 = __shfl_sync(0xFFFFFFFFu, c, j);
            float4 v0 = ld_h4(x, (size_t)s0 * 32 + lane);
            acc.x += v0.x; acc.y += v0.y; acc.z += v0.z; acc.w += v0.w;
        }
    }
    return acc;
}

// layer-1 agg: h'[v] = dinv[v] * relu(dinv[v]*acc + b0)
__global__ __launch_bounds__(256)
void k_agg(const __half* __restrict__ x, const float* __restrict__ bias,
           __half* __restrict__ out, int n) {
    int gw   = (blockIdx.x * blockDim.x + threadIdx.x) >> 5;
    int lane = threadIdx.x & 31;
    if (gw >= n) return;
    float4 acc = agg_core(x, gw, lane);
    float dv = g_dinv[gw];
    float4 bv = *reinterpret_cast<const float4*>(bias + lane * 4);
    float o0 = fmaxf(fmaf(acc.x, dv, bv.x), 0.f) * dv;
    float o1 = fmaxf(fmaf(acc.y, dv, bv.y), 0.f) * dv;
    float o2 = fmaxf(fmaf(acc.z, dv, bv.z), 0.f) * dv;
    float o3 = fmaxf(fmaf(acc.w, dv, bv.w), 0.f) * dv;
    uint2 u;
    __half2 h0 = __floats2half2_rn(o0, o1);
    __half2 h1 = __floats2half2_rn(o2, o3);
    u.x = *reinterpret_cast<uint32_t*>(&h0);
    u.y = *reinterpret_cast<uint32_t*>(&h1);
    reinterpret_cast<uint2*>(out)[(size_t)gw * 32 + lane] = u;
}

// layer-2 agg (compact): a2[slot] = dinv[v] * acc  (fp16)
__global__ __launch_bounds__(256)
void k_agg_sel(const __half* __restrict__ x, __half* __restrict__ out) {
    int gw   = (blockIdx.x * blockDim.x + threadIdx.x) >> 5;
    int lane = threadIdx.x & 31;
    if (gw >= g_cnt) return;
    int node = g_list[gw];
    float4 acc = agg_core(x, node, lane);
    float dv = g_dinv[node];
    uint2 u;
    __half2 h0 = __floats2half2_rn(acc.x * dv, acc.y * dv);
    __half2 h1 = __floats2half2_rn(acc.z * dv, acc.w * dv);
    u.x = *reinterpret_cast<uint32_t*>(&h0);
    u.y = *reinterpret_cast<uint32_t*>(&h1);
    reinterpret_cast<uint2*>(out)[(size_t)gw * 32 + lane] = u;
}

// ---------------- final gather ----------------
__global__ __launch_bounds__(256)
void k_gather(const float* __restrict__ z, const float* __restrict__ emb,
              const int* __restrict__ seq, float* __restrict__ out, int S) {
    int t = blockIdx.x * blockDim.x + threadIdx.x;
    int pos = t >> 5, lane = t & 31;
    if (pos >= S) return;
    int v = seq[pos];
    const float4* srcp;
    size_t row;
    if (v >= 0) { srcp = reinterpret_cast<const float4*>(z);   row = (size_t)g_slot[v]; }
    else        { srcp = reinterpret_cast<const float4*>(emb); row = (size_t)(v + OFFS + NUM_NODES); }
    reinterpret_cast<float4*>(out)[(size_t)pos * 32 + lane] = srcp[row * 32 + lane];
}

// ---------------- host launch ----------------
extern "C" void kernel_launch(void* const* d_in, const int* in_sizes, int n_in,
                              void* d_out, int out_size) {
    const float* emb = (const float*)d_in[0];
    const float* W0  = (const float*)d_in[1];
    const float* b0  = (const float*)d_in[2];
    const float* W1  = (const float*)d_in[3];
    const float* b1  = (const float*)d_in[4];
    const int*   ei  = (const int*)d_in[5];
    const int*   seq = (const int*)d_in[6];

    int E = in_sizes[5] / 2;
    int S = in_sizes[6];
    const int* src = ei;
    const int* dst = ei + E;

    float *z = nullptr;
    __half *y16 = nullptr, *h16 = nullptr, *a2 = nullptr;
    __nv_bfloat16 *w0h = nullptr, *w0l = nullptr, *w1h = nullptr, *w1l = nullptr;
    cudaGetSymbolAddress((void**)&z,   g_z);
    cudaGetSymbolAddress((void**)&y16, g_y16);
    cudaGetSymbolAddress((void**)&h16, g_h16);
    cudaGetSymbolAddress((void**)&a2,  g_a2);
    cudaGetSymbolAddress((void**)&w0h, g_w0h);
    cudaGetSymbolAddress((void**)&w0l, g_w0l);
    cudaGetSymbolAddress((void**)&w1h, g_w1h);
    cudaGetSymbolAddress((void**)&w1l, g_w1l);

    cudaFuncSetAttribute((const void*)k_gemm<false, true, false, false>,
                         cudaFuncAttributeMaxDynamicSharedMemorySize, GEMM_SMEM);
    cudaFuncSetAttribute((const void*)k_gemm<true, false, true, true>,
                         cudaFuncAttributeMaxDynamicSharedMemorySize, GEMM_SMEM);

    int dev = 0, nsm = 0, occ = 0;
    cudaGetDevice(&dev);
    cudaDeviceGetAttribute(&nsm, cudaDevAttrMultiProcessorCount, dev);
    cudaOccupancyMaxActiveBlocksPerMultiprocessor(&occ, k_prep, 256, 0);
    if (occ < 1) occ = 1;
    if (occ > 8) occ = 8;
    int nblk = nsm * occ;
    if (nblk > 2048) nblk = 2048;
    int chunk = (NUM_NODES + nblk - 1) / nblk;

    // 0) all prep in one persistent kernel
    k_prep<<<nblk, 256>>>(W0, W1, src, dst, seq, E, S, nblk, chunk);
    // 1) Y0' = dinv * (emb @ W0)
    k_gemm<false, true, false, false><<<(NUM_NODES + 127) / 128, 256, GEMM_SMEM>>>(
        emb, w0h, w0l, nullptr, y16, NUM_NODES);
    // 2) h' = dinv * relu(agg(Y0') + b0)
    k_agg<<<(NUM_NODES * 32 + 255) / 256, 256>>>(y16, b0, h16, NUM_NODES);
    // 3) a2 = agg_sel(h')  (compact, fp16)   <-- ncu index 3
    k_agg_sel<<<(MAX_SEQ * 32 + 255) / 256, 256>>>(h16, a2);
    // 4) z = a2 @ W1 + b1  (compact, fp32 out)
    k_gemm<true, false, true, true><<<(MAX_SEQ + 127) / 128, 256, GEMM_SMEM>>>(
        a2, w1h, w1l, b1, z, 0);
    // 5) gather
    k_gather<<<(S * 32 + 255) / 256, 256>>>(z, emb, seq, (float*)d_out, S);
}

// round 12
// speedup vs baseline: 2.0211x; 1.0097x over previous
#include <cuda_runtime.h>
#include <cuda_bf16.h>
#include <cuda_fp16.h>
#include <cstdint>

#define NUM_NODES 100000
#define HIDDEN    128
#define OFFS      2
#define MAX_E     1700000
#define MAX_SEQ   32768

// ---------------- device scratch ----------------
__device__ int   g_deg[NUM_NODES];
__device__ int   g_fill[NUM_NODES];       // after prep: CSR write cursor (= rowptr)
__device__ int   g_rowptr[NUM_NODES + 1];
__device__ int   g_blksum[2048];
__device__ int   g_colidx[MAX_E];
__device__ float g_dinv[NUM_NODES];
__device__ int   g_need[NUM_NODES];
__device__ int   g_slot[NUM_NODES];
__device__ int   g_list[MAX_SEQ];
__device__ int   g_cnt;
__device__ unsigned g_bar;
__device__ unsigned g_gen;
__device__ __half g_y16[(size_t)NUM_NODES * HIDDEN];
__device__ __half g_h16[(size_t)NUM_NODES * HIDDEN];
__device__ __half g_a2[(size_t)MAX_SEQ * HIDDEN];
__device__ float  g_z[(size_t)MAX_SEQ * HIDDEN];
__device__ __nv_bfloat16 g_w0h[HIDDEN * HIDDEN];
__device__ __nv_bfloat16 g_w0l[HIDDEN * HIDDEN];
__device__ __nv_bfloat16 g_w1h[HIDDEN * HIDDEN];
__device__ __nv_bfloat16 g_w1l[HIDDEN * HIDDEN];

// ---------------- helpers ----------------
__device__ __forceinline__ uint32_t smem_u32(const void* p) {
    uint32_t a;
    asm("{ .reg .u64 t; cvta.to.shared.u64 t, %1; cvt.u32.u64 %0, t; }" : "=r"(a) : "l"(p));
    return a;
}
__device__ __forceinline__ void ldsm_x4(uint32_t addr, uint32_t& r0, uint32_t& r1,
                                        uint32_t& r2, uint32_t& r3) {
    asm volatile("ldmatrix.sync.aligned.m8n8.x4.shared.b16 {%0,%1,%2,%3}, [%4];"
                 : "=r"(r0), "=r"(r1), "=r"(r2), "=r"(r3) : "r"(addr));
}
__device__ __forceinline__ void mma_bf16(float* c, const uint32_t* a, uint32_t b0, uint32_t b1) {
    asm volatile(
        "mma.sync.aligned.m16n8k16.row.col.f32.bf16.bf16.f32 "
        "{%0,%1,%2,%3}, {%4,%5,%6,%7}, {%8,%9}, {%0,%1,%2,%3};"
        : "+f"(c[0]), "+f"(c[1]), "+f"(c[2]), "+f"(c[3])
        : "r"(a[0]), "r"(a[1]), "r"(a[2]), "r"(a[3]), "r"(b0), "r"(b1));
}
__device__ __forceinline__ float4 ld_h4(const __half* __restrict__ x, size_t idx4) {
    uint2 u = reinterpret_cast<const uint2*>(x)[idx4];
    __half2 a = *reinterpret_cast<__half2*>(&u.x);
    __half2 b = *reinterpret_cast<__half2*>(&u.y);
    float2 fa = __half22float2(a), fb = __half22float2(b);
    return make_float4(fa.x, fa.y, fb.x, fb.y);
}
__device__ __forceinline__ void grid_barrier(int nblk) {
    __syncthreads();
    if (threadIdx.x == 0) {
        __threadfence();
        unsigned gen = *(volatile unsigned*)&g_gen;
        if (atomicAdd(&g_bar, 1u) == (unsigned)nblk - 1u) {
            atomicExch(&g_bar, 0u);
            __threadfence();
            atomicAdd(&g_gen, 1u);
        } else {
            while (*(volatile unsigned*)&g_gen == gen) { __nanosleep(64); }
            __threadfence();
        }
    }
    __syncthreads();
}

// ---------------- persistent prep: everything except CSR fill ----------------
__global__ __launch_bounds__(256, 8)
void k_prep(const float* __restrict__ W0, const float* __restrict__ W1,
            const int* __restrict__ dst, const int* __restrict__ seq,
            int E, int S, int nblk, int chunk) {
    const int tid = threadIdx.x, bid = blockIdx.x;
    const int gtid = bid * 256 + tid;
    const int gstride = nblk * 256;
    __shared__ int sbuf[256];

    // P0: zero counters + weight split
    for (int i = gtid; i < NUM_NODES; i += gstride) {
        g_deg[i] = 0; g_need[i] = 0;
    }
    if (gtid == 0) g_cnt = 0;
    for (int i = gtid; i < 2 * HIDDEN * HIDDEN; i += gstride) {
        int which = i >> 14, idx = i & 16383;   // idx = k*128+n
        float w = (which ? W1 : W0)[idx];
        int k = idx >> 7, n = idx & 127;
        __nv_bfloat16 h = __float2bfloat16(w);
        (which ? g_w1h : g_w0h)[n * 128 + k] = h;
        (which ? g_w1l : g_w0l)[n * 128 + k] = __float2bfloat16(w - __bfloat162float(h));
    }
    grid_barrier(nblk);

    // P1: degree count + mark needed
    for (int e = gtid; e < E; e += gstride) atomicAdd(&g_deg[dst[e]], 1);
    for (int p = gtid; p < S; p += gstride) {
        int v = seq[p];
        if (v >= 0) g_need[v] = 1;
    }
    grid_barrier(nblk);

    // P2: per-block chunk sums
    {
        int start = bid * chunk;
        int len = NUM_NODES - start;
        if (len > chunk) len = chunk;
        int acc = 0;
        for (int i = tid; i < len; i += 256) acc += g_deg[start + i];
        sbuf[tid] = acc;
        __syncthreads();
        #pragma unroll
        for (int off = 128; off > 0; off >>= 1) {
            if (tid < off) sbuf[tid] += sbuf[tid + off];
            __syncthreads();
        }
        if (tid == 0) g_blksum[bid] = sbuf[0];
    }
    grid_barrier(nblk);

    // P3: block 0 exclusive-scans chunk sums
    if (bid == 0) {
        int ele = (nblk + 255) >> 8;
        int base_i = tid * ele;
        int vals[8];
        int tsum = 0;
        for (int q = 0; q < ele && q < 8; q++) {
            int ii = base_i + q;
            vals[q] = (ii < nblk) ? g_blksum[ii] : 0;
            tsum += vals[q];
        }
        sbuf[tid] = tsum;
        __syncthreads();
        #pragma unroll
        for (int off = 1; off < 256; off <<= 1) {
            int t = (tid >= off) ? sbuf[tid - off] : 0;
            __syncthreads();
            sbuf[tid] += t;
            __syncthreads();
        }
        int run = sbuf[tid] - tsum;
        for (int q = 0; q < ele && q < 8; q++) {
            int ii = base_i + q;
            if (ii < nblk) g_blksum[ii] = run;
            run += vals[q];
        }
    }
    grid_barrier(nblk);

    // P4: chunk exclusive scan -> rowptr + fill cursor, dinv, compact list
    {
        int start = bid * chunk;
        int len = NUM_NODES - start;
        if (len > chunk) len = chunk;
        if (len < 0) len = 0;
        int run = (start < NUM_NODES) ? g_blksum[bid] : 0;
        for (int base = 0; base < chunk; base += 256) {
            int li = base + tid;
            int idx = start + li;
            int val = (li < len) ? g_deg[idx] : 0;
            sbuf[tid] = val;
            __syncthreads();
            #pragma unroll
            for (int off = 1; off < 256; off <<= 1) {
                int t = (tid >= off) ? sbuf[tid - off] : 0;
                __syncthreads();
                sbuf[tid] += t;
                __syncthreads();
            }
            int excl = sbuf[tid] - val;
            if (li < len) {
                int rp = run + excl;
                g_rowptr[idx] = rp;
                g_fill[idx]   = rp;   // write cursor for k_fill
                g_dinv[idx] = rsqrtf((float)(val + 1));
                if (g_need[idx]) {
                    int s = atomicAdd(&g_cnt, 1);
                    g_slot[idx] = s;
                    g_list[s] = idx;
                }
            }
            int tot = sbuf[255];
            __syncthreads();
            run += tot;
        }
        if (gtid == 0) g_rowptr[NUM_NODES] = E;
    }
}

// ---------------- CSR fill (runs concurrently with gemm1 on a forked stream) ----------------
__global__ __launch_bounds__(256)
void k_fill(const int* __restrict__ src, const int* __restrict__ dst, int E) {
    int e = blockIdx.x * 256 + threadIdx.x;
    if (e < E) {
        int p = atomicAdd(&g_fill[dst[e]], 1);
        g_colidx[p] = src[e];
    }
}

// ---------------- bf16x3 tensor GEMM (split A in-smem) ----------------
#define LDS_STRIDE 136
#define TILE_HALFS (128 * LDS_STRIDE)
#define GEMM_SMEM  (4 * TILE_HALFS * 2)

template <bool FP16IN, bool SCALED, bool COMPACT, bool FOUT>
__global__ __launch_bounds__(256)
void k_gemm(const void* __restrict__ Av,
            const __nv_bfloat16* __restrict__ Bh, const __nv_bfloat16* __restrict__ Bl,
            const float* __restrict__ bias, void* __restrict__ Cv, int Mfix) {
    const int M = COMPACT ? g_cnt : Mfix;
    const int brow = blockIdx.x * 128;
    if (brow >= M) return;

    extern __shared__ __align__(16) __nv_bfloat16 sm[];
    __nv_bfloat16* sAh = sm;
    __nv_bfloat16* sAl = sm + TILE_HALFS;
    __nv_bfloat16* sBh = sm + 2 * TILE_HALFS;
    __nv_bfloat16* sBl = sm + 3 * TILE_HALFS;

    const int tid = threadIdx.x, wid = tid >> 5, lane = tid & 31;

    for (int i = tid; i < 2048; i += 256) {
        int r  = i >> 4;
        int c8 = (i & 15) << 3;
        int d  = r * LDS_STRIDE + c8;
        int grow = brow + r;
        float f[8];
        if (grow < M) {
            if (FP16IN) {
                const __half* A = (const __half*)Av;
                uint4 v = *reinterpret_cast<const uint4*>(A + (size_t)grow * 128 + c8);
                const __half2* hp = reinterpret_cast<const __half2*>(&v);
                #pragma unroll
                for (int q = 0; q < 4; q++) {
                    float2 fq = __half22float2(hp[q]);
                    f[q * 2] = fq.x; f[q * 2 + 1] = fq.y;
                }
            } else {
                const float* A = (const float*)Av;
                float4 a0 = *reinterpret_cast<const float4*>(A + (size_t)grow * 128 + c8);
                float4 a1 = *reinterpret_cast<const float4*>(A + (size_t)grow * 128 + c8 + 4);
                f[0] = a0.x; f[1] = a0.y; f[2] = a0.z; f[3] = a0.w;
                f[4] = a1.x; f[5] = a1.y; f[6] = a1.z; f[7] = a1.w;
            }
        } else {
            #pragma unroll
            for (int q = 0; q < 8; q++) f[q] = 0.f;
        }
        __align__(16) unsigned short hh[8];
        __align__(16) unsigned short ll[8];
        #pragma unroll
        for (int q = 0; q < 8; q++) {
            __nv_bfloat16 hi = __float2bfloat16(f[q]);
            __nv_bfloat16 lo = __float2bfloat16(f[q] - __bfloat162float(hi));
            hh[q] = __bfloat16_as_ushort(hi);
            ll[q] = __bfloat16_as_ushort(lo);
        }
        *reinterpret_cast<ushort4*>(sAh + d)     = *reinterpret_cast<ushort4*>(hh);
        *reinterpret_cast<ushort4*>(sAh + d + 4) = *reinterpret_cast<ushort4*>(hh + 4);
        *reinterpret_cast<ushort4*>(sAl + d)     = *reinterpret_cast<ushort4*>(ll);
        *reinterpret_cast<ushort4*>(sAl + d + 4) = *reinterpret_cast<ushort4*>(ll + 4);
        *reinterpret_cast<uint4*>(sBh + d) =
            *reinterpret_cast<const uint4*>(Bh + (size_t)r * 128 + c8);
        *reinterpret_cast<uint4*>(sBl + d) =
            *reinterpret_cast<const uint4*>(Bl + (size_t)r * 128 + c8);
    }
    __syncthreads();

    const int mb = (wid & 3) * 32;
    const int nb = (wid >> 2) * 64;

    float acc[2][8][4];
    #pragma unroll
    for (int i = 0; i < 2; i++)
        #pragma unroll
        for (int j = 0; j < 8; j++)
            #pragma unroll
            for (int q = 0; q < 4; q++) acc[i][j][q] = 0.0f;

    const int lrow  = lane & 15;
    const int lbyte = (lane >> 4) << 4;

    #pragma unroll
    for (int pass = 0; pass < 3; pass++) {
        const __nv_bfloat16* pA = (pass == 1) ? sAl : sAh;
        const __nv_bfloat16* pB = (pass == 2) ? sBl : sBh;
        #pragma unroll
        for (int k16 = 0; k16 < 8; k16++) {
            int kb = k16 * 16;
            uint32_t a[2][4];
            #pragma unroll
            for (int i = 0; i < 2; i++) {
                uint32_t ad = smem_u32(pA + (mb + i * 16 + lrow) * LDS_STRIDE + kb) + lbyte;
                ldsm_x4(ad, a[i][0], a[i][1], a[i][2], a[i][3]);
            }
            uint32_t b[4][4];
            #pragma unroll
            for (int j = 0; j < 4; j++) {
                uint32_t ad = smem_u32(pB + (nb + j * 16 + lrow) * LDS_STRIDE + kb) + lbyte;
                ldsm_x4(ad, b[j][0], b[j][1], b[j][2], b[j][3]);
            }
            #pragma unroll
            for (int i = 0; i < 2; i++)
                #pragma unroll
                for (int j = 0; j < 4; j++) {
                    mma_bf16(acc[i][j * 2 + 0], a[i], b[j][0], b[j][2]);
                    mma_bf16(acc[i][j * 2 + 1], a[i], b[j][1], b[j][3]);
                }
        }
    }

    const int tr = lane >> 2, tc = (lane & 3) * 2;
    #pragma unroll
    for (int i = 0; i < 2; i++) {
        int row0 = brow + mb + i * 16 + tr;
        float s0 = 1.f, s1 = 1.f;
        if (SCALED) {
            if (row0 < M)     s0 = g_dinv[row0];
            if (row0 + 8 < M) s1 = g_dinv[row0 + 8];
        }
        #pragma unroll
        for (int j = 0; j < 8; j++) {
            int col = nb + j * 8 + tc;
            if (FOUT) {
                float* C = (float*)Cv;
                float bx = bias[col], by = bias[col + 1];
                if (row0 < M) {
                    float2 o = make_float2(acc[i][j][0] + bx, acc[i][j][1] + by);
                    *reinterpret_cast<float2*>(C + (size_t)row0 * 128 + col) = o;
                }
                if (row0 + 8 < M) {
                    float2 o = make_float2(acc[i][j][2] + bx, acc[i][j][3] + by);
                    *reinterpret_cast<float2*>(C + (size_t)(row0 + 8) * 128 + col) = o;
                }
            } else {
                __half* C = (__half*)Cv;
                if (row0 < M)
                    *reinterpret_cast<__half2*>(C + (size_t)row0 * 128 + col) =
                        __floats2half2_rn(acc[i][j][0] * s0, acc[i][j][1] * s0);
                if (row0 + 8 < M)
                    *reinterpret_cast<__half2*>(C + (size_t)(row0 + 8) * 128 + col) =
                        __floats2half2_rn(acc[i][j][2] * s1, acc[i][j][3] * s1);
            }
        }
    }
}

// ---------------- weightless aggregation: 8-deep MLP groups + fp16 pairing ----------------
__device__ __forceinline__ float4 agg_core(const __half* __restrict__ x, int node, int lane) {
    float4 acc = ld_h4(x, (size_t)node * 32 + lane);   // self term (pre-scaled)
    const uint2* xr = reinterpret_cast<const uint2*>(x);
    int b = g_rowptr[node], e = g_rowptr[node + 1];
    for (int base = b; base < e; base += 32) {
        int m = min(32, e - base);
        int c = (lane < m) ? g_colidx[base + lane] : 0;
        int j = 0;
        // 8-edge groups: 8 independent LDGs in flight, 2-level fp16 reduce
        for (; j + 8 <= m; j += 8) {
            uint2 u[8];
            #pragma unroll
            for (int q = 0; q < 8; q++) {
                int s = __shfl_sync(0xFFFFFFFFu, c, j + q);
                u[q] = xr[(size_t)s * 32 + lane];
            }
            __half2 p0x = __hadd2(*reinterpret_cast<__half2*>(&u[0].x),
                                  *reinterpret_cast<__half2*>(&u[1].x));
            __half2 p0y = __hadd2(*reinterpret_cast<__half2*>(&u[0].y),
                                  *reinterpret_cast<__half2*>(&u[1].y));
            __half2 p1x = __hadd2(*reinterpret_cast<__half2*>(&u[2].x),
                                  *reinterpret_cast<__half2*>(&u[3].x));
            __half2 p1y = __hadd2(*reinterpret_cast<__half2*>(&u[2].y),
                                  *reinterpret_cast<__half2*>(&u[3].y));
            __half2 p2x = __hadd2(*reinterpret_cast<__half2*>(&u[4].x),
                                  *reinterpret_cast<__half2*>(&u[5].x));
            __half2 p2y = __hadd2(*reinterpret_cast<__half2*>(&u[4].y),
                                  *reinterpret_cast<__half2*>(&u[5].y));
            __half2 p3x = __hadd2(*reinterpret_cast<__half2*>(&u[6].x),
                                  *reinterpret_cast<__half2*>(&u[7].x));
            __half2 p3y = __hadd2(*reinterpret_cast<__half2*>(&u[6].y),
                                  *reinterpret_cast<__half2*>(&u[7].y));
            __half2 q0x = __hadd2(p0x, p1x);
            __half2 q0y = __hadd2(p0y, p1y);
            __half2 q1x = __hadd2(p2x, p3x);
            __half2 q1y = __hadd2(p2y, p3y);
            float2 f0 = __half22float2(q0x), f1 = __half22float2(q0y);
            float2 g0 = __half22float2(q1x), g1 = __half22float2(q1y);
            acc.x += f0.x + g0.x;
            acc.y += f0.y + g0.y;
            acc.z += f1.x + g1.x;
            acc.w += f1.y + g1.y;
        }
        // 4-edge groups
        for (; j + 4 <= m; j += 4) {
            uint2 u[4];
            #pragma unroll
            for (int q = 0; q < 4; q++) {
                int s = __shfl_sync(0xFFFFFFFFu, c, j + q);
                u[q] = xr[(size_t)s * 32 + lane];
            }
            __half2 p0 = __hadd2(*reinterpret_cast<__half2*>(&u[0].x),
                                 *reinterpret_cast<__half2*>(&u[1].x));
            __half2 p1 = __hadd2(*reinterpret_cast<__half2*>(&u[0].y),
                                 *reinterpret_cast<__half2*>(&u[1].y));
            __half2 q0 = __hadd2(*reinterpret_cast<__half2*>(&u[2].x),
                                 *reinterpret_cast<__half2*>(&u[3].x));
            __half2 q1 = __hadd2(*reinterpret_cast<__half2*>(&u[2].y),
                                 *reinterpret_cast<__half2*>(&u[3].y));
            float2 f0 = __half22float2(p0), f1 = __half22float2(p1);
            float2 g0 = __half22float2(q0), g1 = __half22float2(q1);
            acc.x += f0.x + g0.x;
            acc.y += f0.y + g0.y;
            acc.z += f1.x + g1.x;
            acc.w += f1.y + g1.y;
        }
        for (; j < m; j++) {
            int s0 = __shfl_sync(0xFFFFFFFFu, c, j);
            float4 v0 = ld_h4(x, (size_t)s0 * 32 + lane);
            acc.x += v0.x; acc.y += v0.y; acc.z += v0.z; acc.w += v0.w;
        }
    }
    return acc;
}

// layer-1 agg: h'[v] = dinv[v] * relu(dinv[v]*acc + b0)
__global__ __launch_bounds__(256)
void k_agg(const __half* __restrict__ x, const float* __restrict__ bias,
           __half* __restrict__ out, int n) {
    int gw   = (blockIdx.x * blockDim.x + threadIdx.x) >> 5;
    int lane = threadIdx.x & 31;
    if (gw >= n) return;
    float4 acc = agg_core(x, gw, lane);
    float dv = g_dinv[gw];
    float4 bv = *reinterpret_cast<const float4*>(bias + lane * 4);
    float o0 = fmaxf(fmaf(acc.x, dv, bv.x), 0.f) * dv;
    float o1 = fmaxf(fmaf(acc.y, dv, bv.y), 0.f) * dv;
    float o2 = fmaxf(fmaf(acc.z, dv, bv.z), 0.f) * dv;
    float o3 = fmaxf(fmaf(acc.w, dv, bv.w), 0.f) * dv;
    uint2 u;
    __half2 h0 = __floats2half2_rn(o0, o1);
    __half2 h1 = __floats2half2_rn(o2, o3);
    u.x = *reinterpret_cast<uint32_t*>(&h0);
    u.y = *reinterpret_cast<uint32_t*>(&h1);
    reinterpret_cast<uint2*>(out)[(size_t)gw * 32 + lane] = u;
}

// layer-2 agg (compact): a2[slot] = dinv[v] * acc  (fp16)
__global__ __launch_bounds__(256)
void k_agg_sel(const __half* __restrict__ x, __half* __restrict__ out) {
    int gw   = (blockIdx.x * blockDim.x + threadIdx.x) >> 5;
    int lane = threadIdx.x & 31;
    if (gw >= g_cnt) return;
    int node = g_list[gw];
    float4 acc = agg_core(x, node, lane);
    float dv = g_dinv[node];
    uint2 u;
    __half2 h0 = __floats2half2_rn(acc.x * dv, acc.y * dv);
    __half2 h1 = __floats2half2_rn(acc.z * dv, acc.w * dv);
    u.x = *reinterpret_cast<uint32_t*>(&h0);
    u.y = *reinterpret_cast<uint32_t*>(&h1);
    reinterpret_cast<uint2*>(out)[(size_t)gw * 32 + lane] = u;
}

// ---------------- final gather ----------------
__global__ __launch_bounds__(256)
void k_gather(const float* __restrict__ z, const float* __restrict__ emb,
              const int* __restrict__ seq, float* __restrict__ out, int S) {
    int t = blockIdx.x * blockDim.x + threadIdx.x;
    int pos = t >> 5, lane = t & 31;
    if (pos >= S) return;
    int v = seq[pos];
    const float4* srcp;
    size_t row;
    if (v >= 0) { srcp = reinterpret_cast<const float4*>(z);   row = (size_t)g_slot[v]; }
    else        { srcp = reinterpret_cast<const float4*>(emb); row = (size_t)(v + OFFS + NUM_NODES); }
    reinterpret_cast<float4*>(out)[(size_t)pos * 32 + lane] = srcp[row * 32 + lane];
}

// ---------------- host launch ----------------
extern "C" void kernel_launch(void* const* d_in, const int* in_sizes, int n_in,
                              void* d_out, int out_size) {
    const float* emb = (const float*)d_in[0];
    const float* W0  = (const float*)d_in[1];
    const float* b0  = (const float*)d_in[2];
    const float* W1  = (const float*)d_in[3];
    const float* b1  = (const float*)d_in[4];
    const int*   ei  = (const int*)d_in[5];
    const int*   seq = (const int*)d_in[6];

    int E = in_sizes[5] / 2;
    int S = in_sizes[6];
    const int* src = ei;
    const int* dst = ei + E;

    float *z = nullptr;
    __half *y16 = nullptr, *h16 = nullptr, *a2 = nullptr;
    __nv_bfloat16 *w0h = nullptr, *w0l = nullptr, *w1h = nullptr, *w1l = nullptr;
    cudaGetSymbolAddress((void**)&z,   g_z);
    cudaGetSymbolAddress((void**)&y16, g_y16);
    cudaGetSymbolAddress((void**)&h16, g_h16);
    cudaGetSymbolAddress((void**)&a2,  g_a2);
    cudaGetSymbolAddress((void**)&w0h, g_w0h);
    cudaGetSymbolAddress((void**)&w0l, g_w0l);
    cudaGetSymbolAddress((void**)&w1h, g_w1h);
    cudaGetSymbolAddress((void**)&w1l, g_w1l);

    cudaFuncSetAttribute((const void*)k_gemm<false, true, false, false>,
                         cudaFuncAttributeMaxDynamicSharedMemorySize, GEMM_SMEM);
    cudaFuncSetAttribute((const void*)k_gemm<true, false, true, true>,
                         cudaFuncAttributeMaxDynamicSharedMemorySize, GEMM_SMEM);

    int dev = 0, nsm = 0, occ = 0;
    cudaGetDevice(&dev);
    cudaDeviceGetAttribute(&nsm, cudaDevAttrMultiProcessorCount, dev);
    cudaOccupancyMaxActiveBlocksPerMultiprocessor(&occ, k_prep, 256, 0);
    if (occ < 1) occ = 1;
    if (occ > 8) occ = 8;
    int nblk = nsm * occ;
    if (nblk > 2048) nblk = 2048;
    int chunk = (NUM_NODES + nblk - 1) / nblk;

    // one-time stream/event setup (constant across calls; no device-memory alloc)
    static bool s_init = false;
    static cudaStream_t s_fill;
    static cudaEvent_t s_evA, s_evB;
    if (!s_init) {
        cudaStreamCreateWithFlags(&s_fill, cudaStreamNonBlocking);
        cudaEventCreateWithFlags(&s_evA, cudaEventDisableTiming);
        cudaEventCreateWithFlags(&s_evB, cudaEventDisableTiming);
        s_init = true;
    }

    // 0) prep (count/scan/dinv/list/cursor/weights) on default stream
    k_prep<<<nblk, 256>>>(W0, W1, dst, seq, E, S, nblk, chunk);
    // fork: fill runs concurrently with gemm1
    cudaEventRecord(s_evA, 0);
    cudaStreamWaitEvent(s_fill, s_evA, 0);
    k_fill<<<(E + 255) / 256, 256, 0, s_fill>>>(src, dst, E);
    cudaEventRecord(s_evB, s_fill);
    // 1) Y0' = dinv * (emb @ W0)   (independent of fill)
    k_gemm<false, true, false, false><<<(NUM_NODES + 127) / 128, 256, GEMM_SMEM>>>(
        emb, w0h, w0l, nullptr, y16, NUM_NODES);
    // join: agg needs colidx
    cudaStreamWaitEvent(0, s_evB, 0);
    // 2) h' = dinv * relu(agg(Y0') + b0)
    k_agg<<<(NUM_NODES * 32 + 255) / 256, 256>>>(y16, b0, h16, NUM_NODES);
    // 3) a2 = agg_sel(h')  (compact, fp16)
    k_agg_sel<<<(MAX_SEQ * 32 + 255) / 256, 256>>>(h16, a2);
    // 4) z = a2 @ W1 + b1  (compact, fp32 out)
    k_gemm<true, false, true, true><<<(MAX_SEQ + 127) / 128, 256, GEMM_SMEM>>>(
        a2, w1h, w1l, b1, z, 0);
    // 5) gather
    k_gather<<<(S * 32 + 255) / 256, 256>>>(z, emb, seq, (float*)d_out, S);
}

// round 13
// speedup vs baseline: 2.0419x; 1.0103x over previous
#include <cuda_runtime.h>
#include <cuda_bf16.h>
#include <cuda_fp16.h>
#include <cstdint>

#define NUM_NODES 100000
#define HIDDEN    128
#define OFFS      2
#define MAX_E     1700000
#define MAX_SEQ   32768

// ---------------- device scratch ----------------
__device__ int   g_deg[NUM_NODES];
__device__ int   g_fill[NUM_NODES];       // after prep: CSR write cursor (= rowptr)
__device__ int   g_rowptr[NUM_NODES + 1];
__device__ int   g_blksum[2048];
__device__ int   g_colidx[MAX_E];
__device__ float g_dinv[NUM_NODES];
__device__ int   g_need[NUM_NODES];
__device__ int   g_slot[NUM_NODES];
__device__ int   g_list[MAX_SEQ];
__device__ int   g_cnt;
__device__ unsigned g_bar;
__device__ unsigned g_gen;
__device__ __half g_y16[(size_t)NUM_NODES * HIDDEN];
__device__ __half g_h16[(size_t)NUM_NODES * HIDDEN];
__device__ __half g_a2[(size_t)MAX_SEQ * HIDDEN];
__device__ float  g_z[(size_t)MAX_SEQ * HIDDEN];
__device__ __nv_bfloat16 g_w0h[HIDDEN * HIDDEN];
__device__ __nv_bfloat16 g_w0l[HIDDEN * HIDDEN];
__device__ __nv_bfloat16 g_w1h[HIDDEN * HIDDEN];
__device__ __nv_bfloat16 g_w1l[HIDDEN * HIDDEN];

// ---------------- helpers ----------------
__device__ __forceinline__ uint32_t smem_u32(const void* p) {
    uint32_t a;
    asm("{ .reg .u64 t; cvta.to.shared.u64 t, %1; cvt.u32.u64 %0, t; }" : "=r"(a) : "l"(p));
    return a;
}
__device__ __forceinline__ void ldsm_x4(uint32_t addr, uint32_t& r0, uint32_t& r1,
                                        uint32_t& r2, uint32_t& r3) {
    asm volatile("ldmatrix.sync.aligned.m8n8.x4.shared.b16 {%0,%1,%2,%3}, [%4];"
                 : "=r"(r0), "=r"(r1), "=r"(r2), "=r"(r3) : "r"(addr));
}
__device__ __forceinline__ void mma_bf16(float* c, const uint32_t* a, uint32_t b0, uint32_t b1) {
    asm volatile(
        "mma.sync.aligned.m16n8k16.row.col.f32.bf16.bf16.f32 "
        "{%0,%1,%2,%3}, {%4,%5,%6,%7}, {%8,%9}, {%0,%1,%2,%3};"
        : "+f"(c[0]), "+f"(c[1]), "+f"(c[2]), "+f"(c[3])
        : "r"(a[0]), "r"(a[1]), "r"(a[2]), "r"(a[3]), "r"(b0), "r"(b1));
}
__device__ __forceinline__ void grid_barrier(int nblk) {
    __syncthreads();
    if (threadIdx.x == 0) {
        __threadfence();
        unsigned gen = *(volatile unsigned*)&g_gen;
        if (atomicAdd(&g_bar, 1u) == (unsigned)nblk - 1u) {
            atomicExch(&g_bar, 0u);
            __threadfence();
            atomicAdd(&g_gen, 1u);
        } else {
            while (*(volatile unsigned*)&g_gen == gen) { __nanosleep(64); }
            __threadfence();
        }
    }
    __syncthreads();
}

// ---------------- persistent prep: everything except CSR fill ----------------
__global__ __launch_bounds__(256, 8)
void k_prep(const float* __restrict__ W0, const float* __restrict__ W1,
            const int* __restrict__ dst, const int* __restrict__ seq,
            int E, int S, int nblk, int chunk) {
    const int tid = threadIdx.x, bid = blockIdx.x;
    const int gtid = bid * 256 + tid;
    const int gstride = nblk * 256;
    __shared__ int sbuf[256];

    for (int i = gtid; i < NUM_NODES; i += gstride) {
        g_deg[i] = 0; g_need[i] = 0;
    }
    if (gtid == 0) g_cnt = 0;
    for (int i = gtid; i < 2 * HIDDEN * HIDDEN; i += gstride) {
        int which = i >> 14, idx = i & 16383;   // idx = k*128+n
        float w = (which ? W1 : W0)[idx];
        int k = idx >> 7, n = idx & 127;
        __nv_bfloat16 h = __float2bfloat16(w);
        (which ? g_w1h : g_w0h)[n * 128 + k] = h;
        (which ? g_w1l : g_w0l)[n * 128 + k] = __float2bfloat16(w - __bfloat162float(h));
    }
    grid_barrier(nblk);

    for (int e = gtid; e < E; e += gstride) atomicAdd(&g_deg[dst[e]], 1);
    for (int p = gtid; p < S; p += gstride) {
        int v = seq[p];
        if (v >= 0) g_need[v] = 1;
    }
    grid_barrier(nblk);

    {
        int start = bid * chunk;
        int len = NUM_NODES - start;
        if (len > chunk) len = chunk;
        int acc = 0;
        for (int i = tid; i < len; i += 256) acc += g_deg[start + i];
        sbuf[tid] = acc;
        __syncthreads();
        #pragma unroll
        for (int off = 128; off > 0; off >>= 1) {
            if (tid < off) sbuf[tid] += sbuf[tid + off];
            __syncthreads();
        }
        if (tid == 0) g_blksum[bid] = sbuf[0];
    }
    grid_barrier(nblk);

    if (bid == 0) {
        int ele = (nblk + 255) >> 8;
        int base_i = tid * ele;
        int vals[8];
        int tsum = 0;
        for (int q = 0; q < ele && q < 8; q++) {
            int ii = base_i + q;
            vals[q] = (ii < nblk) ? g_blksum[ii] : 0;
            tsum += vals[q];
        }
        sbuf[tid] = tsum;
        __syncthreads();
        #pragma unroll
        for (int off = 1; off < 256; off <<= 1) {
            int t = (tid >= off) ? sbuf[tid - off] : 0;
            __syncthreads();
            sbuf[tid] += t;
            __syncthreads();
        }
        int run = sbuf[tid] - tsum;
        for (int q = 0; q < ele && q < 8; q++) {
            int ii = base_i + q;
            if (ii < nblk) g_blksum[ii] = run;
            run += vals[q];
        }
    }
    grid_barrier(nblk);

    {
        int start = bid * chunk;
        int len = NUM_NODES - start;
        if (len > chunk) len = chunk;
        if (len < 0) len = 0;
        int run = (start < NUM_NODES) ? g_blksum[bid] : 0;
        for (int base = 0; base < chunk; base += 256) {
            int li = base + tid;
            int idx = start + li;
            int val = (li < len) ? g_deg[idx] : 0;
            sbuf[tid] = val;
            __syncthreads();
            #pragma unroll
            for (int off = 1; off < 256; off <<= 1) {
                int t = (tid >= off) ? sbuf[tid - off] : 0;
                __syncthreads();
                sbuf[tid] += t;
                __syncthreads();
            }
            int excl = sbuf[tid] - val;
            if (li < len) {
                int rp = run + excl;
                g_rowptr[idx] = rp;
                g_fill[idx]   = rp;
                g_dinv[idx] = rsqrtf((float)(val + 1));
                if (g_need[idx]) {
                    int s = atomicAdd(&g_cnt, 1);
                    g_slot[idx] = s;
                    g_list[s] = idx;
                }
            }
            int tot = sbuf[255];
            __syncthreads();
            run += tot;
        }
        if (gtid == 0) g_rowptr[NUM_NODES] = E;
    }
}

// ---------------- CSR fill (concurrent with gemm1) ----------------
__global__ __launch_bounds__(256)
void k_fill(const int* __restrict__ src, const int* __restrict__ dst, int E) {
    int e = blockIdx.x * 256 + threadIdx.x;
    if (e < E) {
        int p = atomicAdd(&g_fill[dst[e]], 1);
        g_colidx[p] = src[e];
    }
}

// ---------------- bf16x3 tensor GEMM (split A in-smem) ----------------
#define LDS_STRIDE 136
#define TILE_HALFS (128 * LDS_STRIDE)
#define GEMM_SMEM  (4 * TILE_HALFS * 2)

template <bool FP16IN, bool SCALED, bool COMPACT, bool FOUT>
__global__ __launch_bounds__(256)
void k_gemm(const void* __restrict__ Av,
            const __nv_bfloat16* __restrict__ Bh, const __nv_bfloat16* __restrict__ Bl,
            const float* __restrict__ bias, void* __restrict__ Cv, int Mfix) {
    const int M = COMPACT ? g_cnt : Mfix;
    const int brow = blockIdx.x * 128;
    if (brow >= M) return;

    extern __shared__ __align__(16) __nv_bfloat16 sm[];
    __nv_bfloat16* sAh = sm;
    __nv_bfloat16* sAl = sm + TILE_HALFS;
    __nv_bfloat16* sBh = sm + 2 * TILE_HALFS;
    __nv_bfloat16* sBl = sm + 3 * TILE_HALFS;

    const int tid = threadIdx.x, wid = tid >> 5, lane = tid & 31;

    for (int i = tid; i < 2048; i += 256) {
        int r  = i >> 4;
        int c8 = (i & 15) << 3;
        int d  = r * LDS_STRIDE + c8;
        int grow = brow + r;
        float f[8];
        if (grow < M) {
            if (FP16IN) {
                const __half* A = (const __half*)Av;
                uint4 v = *reinterpret_cast<const uint4*>(A + (size_t)grow * 128 + c8);
                const __half2* hp = reinterpret_cast<const __half2*>(&v);
                #pragma unroll
                for (int q = 0; q < 4; q++) {
                    float2 fq = __half22float2(hp[q]);
                    f[q * 2] = fq.x; f[q * 2 + 1] = fq.y;
                }
            } else {
                const float* A = (const float*)Av;
                float4 a0 = *reinterpret_cast<const float4*>(A + (size_t)grow * 128 + c8);
                float4 a1 = *reinterpret_cast<const float4*>(A + (size_t)grow * 128 + c8 + 4);
                f[0] = a0.x; f[1] = a0.y; f[2] = a0.z; f[3] = a0.w;
                f[4] = a1.x; f[5] = a1.y; f[6] = a1.z; f[7] = a1.w;
            }
        } else {
            #pragma unroll
            for (int q = 0; q < 8; q++) f[q] = 0.f;
        }
        __align__(16) unsigned short hh[8];
        __align__(16) unsigned short ll[8];
        #pragma unroll
        for (int q = 0; q < 8; q++) {
            __nv_bfloat16 hi = __float2bfloat16(f[q]);
            __nv_bfloat16 lo = __float2bfloat16(f[q] - __bfloat162float(hi));
            hh[q] = __bfloat16_as_ushort(hi);
            ll[q] = __bfloat16_as_ushort(lo);
        }
        *reinterpret_cast<ushort4*>(sAh + d)     = *reinterpret_cast<ushort4*>(hh);
        *reinterpret_cast<ushort4*>(sAh + d + 4) = *reinterpret_cast<ushort4*>(hh + 4);
        *reinterpret_cast<ushort4*>(sAl + d)     = *reinterpret_cast<ushort4*>(ll);
        *reinterpret_cast<ushort4*>(sAl + d + 4) = *reinterpret_cast<ushort4*>(ll + 4);
        *reinterpret_cast<uint4*>(sBh + d) =
            *reinterpret_cast<const uint4*>(Bh + (size_t)r * 128 + c8);
        *reinterpret_cast<uint4*>(sBl + d) =
            *reinterpret_cast<const uint4*>(Bl + (size_t)r * 128 + c8);
    }
    __syncthreads();

    const int mb = (wid & 3) * 32;
    const int nb = (wid >> 2) * 64;

    float acc[2][8][4];
    #pragma unroll
    for (int i = 0; i < 2; i++)
        #pragma unroll
        for (int j = 0; j < 8; j++)
            #pragma unroll
            for (int q = 0; q < 4; q++) acc[i][j][q] = 0.0f;

    const int lrow  = lane & 15;
    const int lbyte = (lane >> 4) << 4;

    #pragma unroll
    for (int pass = 0; pass < 3; pass++) {
        const __nv_bfloat16* pA = (pass == 1) ? sAl : sAh;
        const __nv_bfloat16* pB = (pass == 2) ? sBl : sBh;
        #pragma unroll
        for (int k16 = 0; k16 < 8; k16++) {
            int kb = k16 * 16;
            uint32_t a[2][4];
            #pragma unroll
            for (int i = 0; i < 2; i++) {
                uint32_t ad = smem_u32(pA + (mb + i * 16 + lrow) * LDS_STRIDE + kb) + lbyte;
                ldsm_x4(ad, a[i][0], a[i][1], a[i][2], a[i][3]);
            }
            uint32_t b[4][4];
            #pragma unroll
            for (int j = 0; j < 4; j++) {
                uint32_t ad = smem_u32(pB + (nb + j * 16 + lrow) * LDS_STRIDE + kb) + lbyte;
                ldsm_x4(ad, b[j][0], b[j][1], b[j][2], b[j][3]);
            }
            #pragma unroll
            for (int i = 0; i < 2; i++)
                #pragma unroll
                for (int j = 0; j < 4; j++) {
                    mma_bf16(acc[i][j * 2 + 0], a[i], b[j][0], b[j][2]);
                    mma_bf16(acc[i][j * 2 + 1], a[i], b[j][1], b[j][3]);
                }
        }
    }

    const int tr = lane >> 2, tc = (lane & 3) * 2;
    #pragma unroll
    for (int i = 0; i < 2; i++) {
        int row0 = brow + mb + i * 16 + tr;
        float s0 = 1.f, s1 = 1.f;
        if (SCALED) {
            if (row0 < M)     s0 = g_dinv[row0];
            if (row0 + 8 < M) s1 = g_dinv[row0 + 8];
        }
        #pragma unroll
        for (int j = 0; j < 8; j++) {
            int col = nb + j * 8 + tc;
            if (FOUT) {
                float* C = (float*)Cv;
                float bx = bias[col], by = bias[col + 1];
                if (row0 < M) {
                    float2 o = make_float2(acc[i][j][0] + bx, acc[i][j][1] + by);
                    *reinterpret_cast<float2*>(C + (size_t)row0 * 128 + col) = o;
                }
                if (row0 + 8 < M) {
                    float2 o = make_float2(acc[i][j][2] + bx, acc[i][j][3] + by);
                    *reinterpret_cast<float2*>(C + (size_t)(row0 + 8) * 128 + col) = o;
                }
            } else {
                __half* C = (__half*)Cv;
                if (row0 < M)
                    *reinterpret_cast<__half2*>(C + (size_t)row0 * 128 + col) =
                        __floats2half2_rn(acc[i][j][0] * s0, acc[i][j][1] * s0);
                if (row0 + 8 < M)
                    *reinterpret_cast<__half2*>(C + (size_t)(row0 + 8) * 128 + col) =
                        __floats2half2_rn(acc[i][j][2] * s1, acc[i][j][3] * s1);
            }
        }
    }
}

// ---------------- aggregation: 2 rows per LDG.128 (16 lanes x uint4 per row) ----------------
// Each lane owns 8 features: fl = lane&15 selects the 16B feature chunk,
// half = lane>>4 selects which edge of a pair this lane accumulates.
// acc[8] fp32; final shfl_xor(16) butterfly merges the two halves.
__device__ __forceinline__ void agg_core8(const __half* __restrict__ x, int node, int lane,
                                          float* acc) {
    const uint4* xr = reinterpret_cast<const uint4*>(x);   // 16 uint4 per 128-feat row
    const int fl = lane & 15, half = lane >> 4;

    #pragma unroll
    for (int q = 0; q < 8; q++) acc[q] = 0.f;
    // self term: half 0 only (avoid double count after butterfly)
    {
        uint4 su = xr[(size_t)node * 16 + fl];
        if (half == 0) {
            __half2* sh = reinterpret_cast<__half2*>(&su);
            #pragma unroll
            for (int q = 0; q < 4; q++) {
                float2 f = __half22float2(sh[q]);
                acc[q * 2]     += f.x;
                acc[q * 2 + 1] += f.y;
            }
        }
    }

    int b = g_rowptr[node], e = g_rowptr[node + 1];
    for (int base = b; base < e; base += 32) {
        int m = min(32, e - base);
        int c = (lane < m) ? g_colidx[base + lane] : 0;
        int j = 0;
        // 4 edges per iteration: two LDG.128, one fp16 pairing level
        for (; j + 4 <= m; j += 4) {
            int sA = __shfl_sync(0xFFFFFFFFu, c, j + half);
            int sB = __shfl_sync(0xFFFFFFFFu, c, j + 2 + half);
            uint4 uA = xr[(size_t)sA * 16 + fl];
            uint4 uB = xr[(size_t)sB * 16 + fl];
            __half2* ha = reinterpret_cast<__half2*>(&uA);
            __half2* hb = reinterpret_cast<__half2*>(&uB);
            #pragma unroll
            for (int q = 0; q < 4; q++) {
                __half2 p = __hadd2(ha[q], hb[q]);
                float2 f = __half22float2(p);
                acc[q * 2]     += f.x;
                acc[q * 2 + 1] += f.y;
            }
        }
        // 2 edges
        for (; j + 2 <= m; j += 2) {
            int s = __shfl_sync(0xFFFFFFFFu, c, j + half);
            uint4 u = xr[(size_t)s * 16 + fl];
            __half2* h = reinterpret_cast<__half2*>(&u);
            #pragma unroll
            for (int q = 0; q < 4; q++) {
                float2 f = __half22float2(h[q]);
                acc[q * 2]     += f.x;
                acc[q * 2 + 1] += f.y;
            }
        }
        // odd tail: half 0 only
        if (j < m) {
            int s = __shfl_sync(0xFFFFFFFFu, c, j);
            uint4 u = xr[(size_t)s * 16 + fl];
            if (half == 0) {
                __half2* h = reinterpret_cast<__half2*>(&u);
                #pragma unroll
                for (int q = 0; q < 4; q++) {
                    float2 f = __half22float2(h[q]);
                    acc[q * 2]     += f.x;
                    acc[q * 2 + 1] += f.y;
                }
            }
        }
    }
    // butterfly: merge the two half-warp partials
    #pragma unroll
    for (int q = 0; q < 8; q++)
        acc[q] += __shfl_xor_sync(0xFFFFFFFFu, acc[q], 16);
}

// layer-1 agg: h'[v] = dinv[v] * relu(dinv[v]*acc + b0)
__global__ __launch_bounds__(256)
void k_agg(const __half* __restrict__ x, const float* __restrict__ bias,
           __half* __restrict__ out, int n) {
    int gw   = (blockIdx.x * blockDim.x + threadIdx.x) >> 5;
    int lane = threadIdx.x & 31;
    if (gw >= n) return;
    float acc[8];
    agg_core8(x, gw, lane, acc);
    float dv = g_dinv[gw];
    const int fl = lane & 15, half = lane >> 4;
    const int col = fl * 8 + half * 4;    // this lane writes 4 features
    float4 bv = *reinterpret_cast<const float4*>(bias + col);
    float o0 = fmaxf(fmaf(acc[half * 4 + 0], dv, bv.x), 0.f) * dv;
    float o1 = fmaxf(fmaf(acc[half * 4 + 1], dv, bv.y), 0.f) * dv;
    float o2 = fmaxf(fmaf(acc[half * 4 + 2], dv, bv.z), 0.f) * dv;
    float o3 = fmaxf(fmaf(acc[half * 4 + 3], dv, bv.w), 0.f) * dv;
    uint2 u;
    __half2 h0 = __floats2half2_rn(o0, o1);
    __half2 h1 = __floats2half2_rn(o2, o3);
    u.x = *reinterpret_cast<uint32_t*>(&h0);
    u.y = *reinterpret_cast<uint32_t*>(&h1);
    *reinterpret_cast<uint2*>(out + (size_t)gw * 128 + col) = u;
}

// layer-2 agg (compact): a2[slot] = dinv[v] * acc  (fp16)
__global__ __launch_bounds__(256)
void k_agg_sel(const __half* __restrict__ x, __half* __restrict__ out) {
    int gw   = (blockIdx.x * blockDim.x + threadIdx.x) >> 5;
    int lane = threadIdx.x & 31;
    if (gw >= g_cnt) return;
    int node = g_list[gw];
    float acc[8];
    agg_core8(x, node, lane, acc);
    float dv = g_dinv[node];
    const int fl = lane & 15, half = lane >> 4;
    const int col = fl * 8 + half * 4;
    uint2 u;
    __half2 h0 = __floats2half2_rn(acc[half * 4 + 0] * dv, acc[half * 4 + 1] * dv);
    __half2 h1 = __floats2half2_rn(acc[half * 4 + 2] * dv, acc[half * 4 + 3] * dv);
    u.x = *reinterpret_cast<uint32_t*>(&h0);
    u.y = *reinterpret_cast<uint32_t*>(&h1);
    *reinterpret_cast<uint2*>(out + (size_t)gw * 128 + col) = u;
}

// ---------------- final gather ----------------
__global__ __launch_bounds__(256)
void k_gather(const float* __restrict__ z, const float* __restrict__ emb,
              const int* __restrict__ seq, float* __restrict__ out, int S) {
    int t = blockIdx.x * blockDim.x + threadIdx.x;
    int pos = t >> 5, lane = t & 31;
    if (pos >= S) return;
    int v = seq[pos];
    const float4* srcp;
    size_t row;
    if (v >= 0) { srcp = reinterpret_cast<const float4*>(z);   row = (size_t)g_slot[v]; }
    else        { srcp = reinterpret_cast<const float4*>(emb); row = (size_t)(v + OFFS + NUM_NODES); }
    reinterpret_cast<float4*>(out)[(size_t)pos * 32 + lane] = srcp[row * 32 + lane];
}

// ---------------- host launch ----------------
extern "C" void kernel_launch(void* const* d_in, const int* in_sizes, int n_in,
                              void* d_out, int out_size) {
    const float* emb = (const float*)d_in[0];
    const float* W0  = (const float*)d_in[1];
    const float* b0  = (const float*)d_in[2];
    const float* W1  = (const float*)d_in[3];
    const float* b1  = (const float*)d_in[4];
    const int*   ei  = (const int*)d_in[5];
    const int*   seq = (const int*)d_in[6];

    int E = in_sizes[5] / 2;
    int S = in_sizes[6];
    const int* src = ei;
    const int* dst = ei + E;

    float *z = nullptr;
    __half *y16 = nullptr, *h16 = nullptr, *a2 = nullptr;
    __nv_bfloat16 *w0h = nullptr, *w0l = nullptr, *w1h = nullptr, *w1l = nullptr;
    cudaGetSymbolAddress((void**)&z,   g_z);
    cudaGetSymbolAddress((void**)&y16, g_y16);
    cudaGetSymbolAddress((void**)&h16, g_h16);
    cudaGetSymbolAddress((void**)&a2,  g_a2);
    cudaGetSymbolAddress((void**)&w0h, g_w0h);
    cudaGetSymbolAddress((void**)&w0l, g_w0l);
    cudaGetSymbolAddress((void**)&w1h, g_w1h);
    cudaGetSymbolAddress((void**)&w1l, g_w1l);

    cudaFuncSetAttribute((const void*)k_gemm<false, true, false, false>,
                         cudaFuncAttributeMaxDynamicSharedMemorySize, GEMM_SMEM);
    cudaFuncSetAttribute((const void*)k_gemm<true, false, true, true>,
                         cudaFuncAttributeMaxDynamicSharedMemorySize, GEMM_SMEM);

    int dev = 0, nsm = 0, occ = 0;
    cudaGetDevice(&dev);
    cudaDeviceGetAttribute(&nsm, cudaDevAttrMultiProcessorCount, dev);
    cudaOccupancyMaxActiveBlocksPerMultiprocessor(&occ, k_prep, 256, 0);
    if (occ < 1) occ = 1;
    if (occ > 8) occ = 8;
    int nblk = nsm * occ;
    if (nblk > 2048) nblk = 2048;
    int chunk = (NUM_NODES + nblk - 1) / nblk;

    static bool s_init = false;
    static cudaStream_t s_fill;
    static cudaEvent_t s_evA, s_evB;
    if (!s_init) {
        cudaStreamCreateWithFlags(&s_fill, cudaStreamNonBlocking);
        cudaEventCreateWithFlags(&s_evA, cudaEventDisableTiming);
        cudaEventCreateWithFlags(&s_evB, cudaEventDisableTiming);
        s_init = true;
    }

    // 0) prep
    k_prep<<<nblk, 256>>>(W0, W1, dst, seq, E, S, nblk, chunk);
    // fork: fill concurrent with gemm1
    cudaEventRecord(s_evA, 0);
    cudaStreamWaitEvent(s_fill, s_evA, 0);
    k_fill<<<(E + 255) / 256, 256, 0, s_fill>>>(src, dst, E);
    cudaEventRecord(s_evB, s_fill);
    // 1) Y0' = dinv * (emb @ W0)
    k_gemm<false, true, false, false><<<(NUM_NODES + 127) / 128, 256, GEMM_SMEM>>>(
        emb, w0h, w0l, nullptr, y16, NUM_NODES);
    cudaStreamWaitEvent(0, s_evB, 0);
    // 2) h' = dinv * relu(agg(Y0') + b0)
    k_agg<<<(NUM_NODES * 32 + 255) / 256, 256>>>(y16, b0, h16, NUM_NODES);
    // 3) a2 = agg_sel(h')
    k_agg_sel<<<(MAX_SEQ * 32 + 255) / 256, 256>>>(h16, a2);
    // 4) z = a2 @ W1 + b1
    k_gemm<true, false, true, true><<<(MAX_SEQ + 127) / 128, 256, GEMM_SMEM>>>(
        a2, w1h, w1l, b1, z, 0);
    // 5) gather
    k_gather<<<(S * 32 + 255) / 256, 256>>>(z, emb, seq, (float*)d_out, S);
}